// round 5
// baseline (speedup 1.0000x reference)
#include <cuda_runtime.h>
#include <cuda_bf16.h>
#include <math.h>

#define B_ 4
#define H_ 8
#define N_ 1024
#define C_ 64
#define INV_SCALE (1.0f/32.0f)

// ---- device scratch ----
__device__ float g_Apart[16][H_][C_][C_];
__device__ float g_bpart[16][H_][C_][4];
__device__ float g_A[H_][C_][C_];
__device__ float g_Bq4[H_][C_][4];
__device__ float g_G[B_][H_][C_][N_];       // 8 MB reduced operand
__device__ float g_WvT[68][H_ * N_];        // Wv^T ++ Wlv^T ++ blv

// ---- packed f32x2 helpers ----
__device__ __forceinline__ unsigned long long pk2(float f) {
    unsigned long long u; unsigned int r = __float_as_uint(f);
    asm("mov.b64 %0, {%1, %1};" : "=l"(u) : "r"(r));
    return u;
}
__device__ __forceinline__ void fma2(unsigned long long& d, unsigned long long a, unsigned long long b) {
    asm("fma.rn.f32x2 %0, %1, %2, %0;" : "+l"(d) : "l"(a), "l"(b));
}
__device__ __forceinline__ void upk(unsigned long long u, float& lo, float& hi) {
    unsigned int a, b;
    asm("mov.b64 {%0,%1}, %2;" : "=r"(a), "=r"(b) : "l"(u));
    lo = __uint_as_float(a); hi = __uint_as_float(b);
}
__device__ __forceinline__ unsigned smem_u32(const void* p) {
    return (unsigned)__cvta_generic_to_shared(p);
}
__device__ __forceinline__ void cp16(unsigned dst, const void* src) {
    asm volatile("cp.async.cg.shared.global [%0], [%1], 16;" :: "r"(dst), "l"(src));
}
__device__ __forceinline__ void cp_commit() {
    asm volatile("cp.async.commit_group;");
}
__device__ __forceinline__ void cp_wait0() {
    asm volatile("cp.async.wait_group 0;" ::: "memory");
}

// ============================================================
// k_prep1: partial A/Bq/bq per 64-d chunk. grid (H,16), 256 thr
// ============================================================
__global__ void k_prep1(const float* __restrict__ Wq, const float* __restrict__ Wk,
                        const float* __restrict__ Wlq, const float* __restrict__ blq) {
    __shared__ float wq_s[64][68];
    __shared__ float wk_s[64][68];
    __shared__ float wl_s[64][4];
    const int h = blockIdx.x, dz = blockIdx.y;
    const int t = threadIdx.x;
    const int rb = h * N_ + dz * 64;

    for (int i = t; i < 64 * 16; i += 256) {
        int r = i >> 4, q = i & 15;
        ((float4*)wq_s[r])[q] = ((const float4*)(Wq + (size_t)(rb + r) * 64))[q];
        ((float4*)wk_s[r])[q] = ((const float4*)(Wk + (size_t)(rb + r) * 64))[q];
    }
    if (t < 64) {
        wl_s[t][0] = Wlq[(size_t)(rb + t) * 3 + 0];
        wl_s[t][1] = Wlq[(size_t)(rb + t) * 3 + 1];
        wl_s[t][2] = Wlq[(size_t)(rb + t) * 3 + 2];
        wl_s[t][3] = blq[rb + t];
    }
    __syncthreads();

    const int rg = t >> 4, cg = t & 15;
    const int c0 = rg * 4, cp0 = cg * 4;
    float acc[4][4] = {};
    #pragma unroll 8
    for (int d = 0; d < 64; d++) {
        float4 qv = *(float4*)&wq_s[d][c0];
        float4 kv = *(float4*)&wk_s[d][cp0];
        acc[0][0]+=qv.x*kv.x; acc[0][1]+=qv.x*kv.y; acc[0][2]+=qv.x*kv.z; acc[0][3]+=qv.x*kv.w;
        acc[1][0]+=qv.y*kv.x; acc[1][1]+=qv.y*kv.y; acc[1][2]+=qv.y*kv.z; acc[1][3]+=qv.y*kv.w;
        acc[2][0]+=qv.z*kv.x; acc[2][1]+=qv.z*kv.y; acc[2][2]+=qv.z*kv.z; acc[2][3]+=qv.z*kv.w;
        acc[3][0]+=qv.w*kv.x; acc[3][1]+=qv.w*kv.y; acc[3][2]+=qv.w*kv.z; acc[3][3]+=qv.w*kv.w;
    }
    #pragma unroll
    for (int i = 0; i < 4; i++)
        *(float4*)&g_Apart[dz][h][c0 + i][cp0] =
            make_float4(acc[i][0], acc[i][1], acc[i][2], acc[i][3]);

    if (t < 64) {
        float s0 = 0.f, s1 = 0.f, s2 = 0.f, s3 = 0.f;
        #pragma unroll 8
        for (int d = 0; d < 64; d++) {
            float wv = wq_s[d][t];
            float4 wl = *(float4*)wl_s[d];
            s0 += wv * wl.x; s1 += wv * wl.y; s2 += wv * wl.z; s3 += wv * wl.w;
        }
        *(float4*)g_bpart[dz][h][t] = make_float4(s0, s1, s2, s3);
    }
}

// ============================================================
// k_prep2: reduce 16 partials. grid (H,16), 256 thr
// ============================================================
__global__ void k_prep2() {
    const int h = blockIdx.x;
    const int e = blockIdx.y * 256 + threadIdx.x;
    const int c = e >> 6, cp = e & 63;
    float s = 0.f;
    #pragma unroll
    for (int dz = 0; dz < 16; dz++) s += g_Apart[dz][h][c][cp];
    g_A[h][c][cp] = s;
    if (blockIdx.y == 0 && threadIdx.x < 64) {
        const int cc = threadIdx.x;
        float4 acc = make_float4(0.f, 0.f, 0.f, 0.f);
        #pragma unroll
        for (int dz = 0; dz < 16; dz++) {
            float4 v = *(float4*)g_bpart[dz][h][cc];
            acc.x += v.x; acc.y += v.y; acc.z += v.z; acc.w += v.w;
        }
        *(float4*)g_Bq4[h][cc] = acc;
    }
}

// ============================================================
// k_wvT: extended transposed V weights. grid 256, 256 thr
// ============================================================
__global__ void k_wvT(const float* __restrict__ Wv, const float* __restrict__ Wlv,
                      const float* __restrict__ blv) {
    __shared__ float tile[32][65];
    const int r0 = blockIdx.x * 32;
    const int t = threadIdx.x;
    for (int i = t; i < 32 * 64; i += 256) {
        int r = i >> 6, c = i & 63;
        tile[r][c] = Wv[(size_t)(r0 + r) * 64 + c];
    }
    __syncthreads();
    for (int i = t; i < 64 * 32; i += 256) {
        int c = i >> 5, r = i & 31;
        g_WvT[c][r0 + r] = tile[r][c];
    }
    if (t < 32) {
        size_t gr = (size_t)(r0 + t);
        g_WvT[64][r0 + t] = Wlv[gr * 3 + 0];
        g_WvT[65][r0 + t] = Wlv[gr * 3 + 1];
        g_WvT[66][r0 + t] = Wlv[gr * 3 + 2];
        g_WvT[67][r0 + t] = blv[gr];
    }
}

// ============================================================
// k_buildG: G = A·ns + Bq·coord + bq. grid (B*H, 16), 256 thr
// ============================================================
__global__ void k_buildG(const float* __restrict__ neighbors,
                         const float* __restrict__ coord) {
    __shared__ float At[64 * 68];
    __shared__ float ns_s[64 * 64];
    __shared__ float cs[3 * 64];
    __shared__ float Bq_s[64 * 4];

    const int b = blockIdx.x >> 3, h = blockIdx.x & 7;
    const int m0 = blockIdx.y * 64;
    const int t = threadIdx.x;

    for (int i = t; i < 64 * 64; i += 256) {
        int c = i >> 6, cp = i & 63;
        At[cp * 68 + c] = g_A[h][c][cp];
    }
    for (int i = t; i < 64 * 16; i += 256) {
        int cp = i >> 4, q = i & 15;
        ((float4*)(ns_s + cp * 64))[q] =
            ((const float4*)(neighbors + ((size_t)b * C_ + cp) * N_ + m0))[q];
    }
    for (int i = t; i < 3 * 16; i += 256) {
        int j = i >> 4, q = i & 15;
        ((float4*)(cs + j * 64))[q] =
            ((const float4*)(coord + ((size_t)b * 3 + j) * N_ + m0))[q];
    }
    for (int i = t; i < 64; i += 256)
        *(float4*)(Bq_s + i * 4) = *(float4*)g_Bq4[h][i];
    __syncthreads();

    const int tc = t >> 5;
    const int tm = t & 31;
    const int c0 = tc * 8;

    float acc[8][2];
    #pragma unroll
    for (int i = 0; i < 8; i++) {
        const int c = c0 + i;
        const float q0 = Bq_s[c * 4], q1 = Bq_s[c * 4 + 1], q2 = Bq_s[c * 4 + 2], bz = Bq_s[c * 4 + 3];
        #pragma unroll
        for (int k = 0; k < 2; k++) {
            const int m = tm * 2 + k;
            acc[i][k] = bz + q0 * cs[m] + q1 * cs[64 + m] + q2 * cs[128 + m];
        }
    }
    #pragma unroll 8
    for (int cp = 0; cp < 64; cp++) {
        float2 nv = ((float2*)(ns_s + cp * 64))[tm];
        float4 a0 = *(float4*)(At + cp * 68 + c0);
        float4 a1 = *(float4*)(At + cp * 68 + c0 + 4);
        acc[0][0]+=a0.x*nv.x; acc[0][1]+=a0.x*nv.y;
        acc[1][0]+=a0.y*nv.x; acc[1][1]+=a0.y*nv.y;
        acc[2][0]+=a0.z*nv.x; acc[2][1]+=a0.z*nv.y;
        acc[3][0]+=a0.w*nv.x; acc[3][1]+=a0.w*nv.y;
        acc[4][0]+=a1.x*nv.x; acc[4][1]+=a1.x*nv.y;
        acc[5][0]+=a1.y*nv.x; acc[5][1]+=a1.y*nv.y;
        acc[6][0]+=a1.z*nv.x; acc[6][1]+=a1.z*nv.y;
        acc[7][0]+=a1.w*nv.x; acc[7][1]+=a1.w*nv.y;
    }
    #pragma unroll
    for (int i = 0; i < 8; i++)
        *((float2*)(&g_G[b][h][c0 + i][m0]) + tm) = make_float2(acc[i][0], acc[i][1]);
}

// ============================================================
// k_main: energy -> softmax -> elementwise V' epilogue
// grid (B*H, N/32), 512 thr; cp.async double-buffered 128-col chunks
// ============================================================
struct SM3 {
    float E[32][1028];       // 131584 B
    float xs[64][32];        //   8192 B
    float nse[68][32];       //   8704 B
    float gw[2][68][132];    //  71808 B   (total 220288 B)
};

__global__ void __launch_bounds__(512, 1) k_main(
    const float* __restrict__ x, const float* __restrict__ neighbors,
    const float* __restrict__ coord, float* __restrict__ out) {
    extern __shared__ char smraw[];
    SM3& s = *reinterpret_cast<SM3*>(smraw);

    const int b = blockIdx.x >> 3, h = blockIdx.x & 7;
    const int n0 = blockIdx.y * 32;
    const int t = threadIdx.x;
    const int w = t >> 5, lane = t & 31;
    const unsigned gwb = smem_u32(&s.gw[0][0][0]);

    for (int i = t; i < 64 * 8; i += 512) {
        int c = i >> 3, q = i & 7;
        ((float4*)s.xs[c])[q]  = ((const float4*)(x + ((size_t)b * C_ + c) * N_ + n0))[q];
        ((float4*)s.nse[c])[q] = ((const float4*)(neighbors + ((size_t)b * C_ + c) * N_ + n0))[q];
    }
    if (t < 24) {
        int j = t >> 3, q = t & 7;
        ((float4*)s.nse[64 + j])[q] = ((const float4*)(coord + ((size_t)b * 3 + j) * N_ + n0))[q];
    } else if (t < 32) {
        ((float4*)s.nse[67])[t - 24] = make_float4(1.f, 1.f, 1.f, 1.f);
    }

    // prologue: async copy G chunk 0 -> buf 0
    {
        for (int i = t; i < 2048; i += 512) {
            int row = i >> 5, q = i & 31;
            cp16(gwb + (unsigned)((row * 132 + q * 4) * 4),
                 &g_G[b][h][row][q * 4]);
        }
        cp_commit();
    }

    // ---- pass 1: E[32][1024], 8 chunks of 128 cols, double-buffered ----
    {
        const int r = t >> 4;           // row 0..31
        const int oct = t & 15;         // cols oct*8..+7
        for (int mc = 0; mc < 8; mc++) {
            cp_wait0();
            __syncthreads();
            if (mc < 7) {
                const int bb = (mc + 1) & 1;
                for (int i = t; i < 2048; i += 512) {
                    int row = i >> 5, q = i & 31;
                    cp16(gwb + (unsigned)((bb * 68 * 132 + row * 132 + q * 4) * 4),
                         &g_G[b][h][row][(mc + 1) * 128 + q * 4]);
                }
                cp_commit();
            }
            const float* bf = &s.gw[mc & 1][0][0];
            unsigned long long a0 = 0, a1 = 0, a2 = 0, a3 = 0;
            #pragma unroll 8
            for (int c = 0; c < 64; c++) {
                unsigned long long xp = pk2(s.xs[c][r]);
                float4 g0 = *(const float4*)(bf + c * 132 + oct * 8);
                float4 g1 = *(const float4*)(bf + c * 132 + oct * 8 + 4);
                fma2(a0, xp, ((unsigned long long*)&g0)[0]);
                fma2(a1, xp, ((unsigned long long*)&g0)[1]);
                fma2(a2, xp, ((unsigned long long*)&g1)[0]);
                fma2(a3, xp, ((unsigned long long*)&g1)[1]);
            }
            float* ep = &s.E[r][mc * 128 + oct * 8];
            float4 o0, o1;
            ((unsigned long long*)&o0)[0] = a0; ((unsigned long long*)&o0)[1] = a1;
            ((unsigned long long*)&o1)[0] = a2; ((unsigned long long*)&o1)[1] = a3;
            *(float4*)ep = o0;
            *(float4*)(ep + 4) = o1;
        }
    }
    __syncwarp();   // E rows 2w,2w+1 written entirely by warp w

    // ---- softmax: warp w handles rows 2w, 2w+1 ----
    #pragma unroll
    for (int rr = 0; rr < 2; rr++) {
        const int r = w * 2 + rr;
        float pv[32];
        float mx = -1e30f;
        #pragma unroll
        for (int j = 0; j < 32; j++) { pv[j] = s.E[r][lane + 32 * j]; mx = fmaxf(mx, pv[j]); }
        #pragma unroll
        for (int o = 16; o; o >>= 1) mx = fmaxf(mx, __shfl_xor_sync(0xffffffffu, mx, o));
        float ss = 0.f;
        #pragma unroll
        for (int j = 0; j < 32; j++) { pv[j] = __expf((pv[j] - mx) * INV_SCALE); ss += pv[j]; }
        #pragma unroll
        for (int o = 16; o; o >>= 1) ss += __shfl_xor_sync(0xffffffffu, ss, o);
        const float rinv = 1.0f / ss;
        #pragma unroll
        for (int j = 0; j < 32; j++) s.E[r][lane + 32 * j] = pv[j] * rinv;
    }

    // prologue: async copy WvT chunk 0 -> buf 0 (overlaps other warps' softmax)
    {
        for (int i = t; i < 2176; i += 512) {
            int row = i >> 5, q = i & 31;
            cp16(gwb + (unsigned)((row * 132 + q * 4) * 4),
                 g_WvT[row] + h * N_ + q * 4);
        }
        cp_commit();
    }

    // ---- pass 2: V'(K=68) * probs, 8 chunks of 128 d-cols ----
    {
        const int ng = t & 7;           // n = ng*4 .. +3
        const int dg = t >> 3;          // d pair = dg*2
        const size_t outbase = (size_t)b * 8192 + (size_t)h * N_;
        for (int dc = 0; dc < 8; dc++) {
            cp_wait0();
            __syncthreads();            // also orders softmax E writes before reads
            if (dc < 7) {
                const int bb = (dc + 1) & 1;
                for (int i = t; i < 2176; i += 512) {
                    int row = i >> 5, q = i & 31;
                    cp16(gwb + (unsigned)((bb * 68 * 132 + row * 132 + q * 4) * 4),
                         g_WvT[row] + h * N_ + (dc + 1) * 128 + q * 4);
                }
                cp_commit();
            }
            const float* bf = &s.gw[dc & 1][0][0];
            unsigned long long a00 = 0, a01 = 0, a10 = 0, a11 = 0;
            #pragma unroll 4
            for (int c = 0; c < 68; c++) {
                float4 nv = *(const float4*)&s.nse[c][ng * 4];
                float2 wv = *(const float2*)(bf + c * 132 + dg * 2);
                unsigned long long n01 = ((unsigned long long*)&nv)[0];
                unsigned long long n23 = ((unsigned long long*)&nv)[1];
                unsigned long long w0 = pk2(wv.x), w1 = pk2(wv.y);
                fma2(a00, w0, n01); fma2(a01, w0, n23);
                fma2(a10, w1, n01); fma2(a11, w1, n23);
            }
            float v0[4], v1[4];
            upk(a00, v0[0], v0[1]); upk(a01, v0[2], v0[3]);
            upk(a10, v1[0], v1[1]); upk(a11, v1[2], v1[3]);
            const int d0 = dc * 128 + dg * 2;
            {
                float4 o = make_float4(v0[0] * s.E[ng * 4 + 0][d0],
                                       v0[1] * s.E[ng * 4 + 1][d0],
                                       v0[2] * s.E[ng * 4 + 2][d0],
                                       v0[3] * s.E[ng * 4 + 3][d0]);
                *(float4*)(out + (outbase + d0) * N_ + n0 + ng * 4) = o;
            }
            {
                float4 o = make_float4(v1[0] * s.E[ng * 4 + 0][d0 + 1],
                                       v1[1] * s.E[ng * 4 + 1][d0 + 1],
                                       v1[2] * s.E[ng * 4 + 2][d0 + 1],
                                       v1[3] * s.E[ng * 4 + 3][d0 + 1]);
                *(float4*)(out + (outbase + d0 + 1) * N_ + n0 + ng * 4) = o;
            }
        }
    }
}

// ============================================================
extern "C" void kernel_launch(void* const* d_in, const int* in_sizes, int n_in,
                              void* d_out, int out_size) {
    const float* coordinate = (const float*)d_in[0];
    const float* x          = (const float*)d_in[1];
    const float* neighbors  = (const float*)d_in[2];
    const float* Wq         = (const float*)d_in[3];
    const float* Wk         = (const float*)d_in[4];
    const float* Wv         = (const float*)d_in[5];
    const float* Wlq        = (const float*)d_in[6];
    const float* blq        = (const float*)d_in[7];
    const float* Wlv        = (const float*)d_in[8];
    const float* blv        = (const float*)d_in[9];
    float* out = (float*)d_out;

    static bool attr_set = false;
    if (!attr_set) {
        cudaFuncSetAttribute(k_main, cudaFuncAttributeMaxDynamicSharedMemorySize, 221184);
        attr_set = true;
    }

    k_prep1<<<dim3(H_, 16), 256>>>(Wq, Wk, Wlq, blq);
    k_prep2<<<dim3(H_, 16), 256>>>();
    k_wvT<<<256, 256>>>(Wv, Wlv, blv);
    k_buildG<<<dim3(B_ * H_, 16), 256>>>(neighbors, coordinate);
    k_main<<<dim3(B_ * H_, 32), 512, sizeof(SM3)>>>(x, neighbors, coordinate, out);
}

// round 8
// speedup vs baseline: 2.1403x; 2.1403x over previous
#include <cuda_runtime.h>
#include <cuda_bf16.h>
#include <math.h>

#define B_ 4
#define H_ 8
#define N_ 1024
#define C_ 64
#define INV_SCALE (1.0f/32.0f)

// ---- device scratch ----
__device__ float g_Apart[16][H_][C_][C_];
__device__ float g_bpart[16][H_][C_][4];
__device__ float g_A[H_][C_][C_];
__device__ float g_Bq4[H_][C_][4];
__device__ float g_G[B_][H_][C_][N_];       // 8 MB reduced operand
__device__ float g_WvT[68][H_ * N_];        // Wv^T ++ Wlv^T ++ blv

// ---- packed f32x2 helpers ----
__device__ __forceinline__ unsigned long long pk2(float f) {
    unsigned long long u; unsigned int r = __float_as_uint(f);
    asm("mov.b64 %0, {%1, %1};" : "=l"(u) : "r"(r));
    return u;
}
__device__ __forceinline__ void fma2(unsigned long long& d, unsigned long long a, unsigned long long b) {
    asm("fma.rn.f32x2 %0, %1, %2, %0;" : "+l"(d) : "l"(a), "l"(b));
}
__device__ __forceinline__ void mul2(unsigned long long& d, unsigned long long a, unsigned long long b) {
    asm("mul.rn.f32x2 %0, %1, %2;" : "=l"(d) : "l"(a), "l"(b));
}
__device__ __forceinline__ void upk(unsigned long long u, float& lo, float& hi) {
    unsigned int a, b;
    asm("mov.b64 {%0,%1}, %2;" : "=r"(a), "=r"(b) : "l"(u));
    lo = __uint_as_float(a); hi = __uint_as_float(b);
}

// ============================================================
// k_prep1: partial A/Bq/bq per 64-d chunk. grid (H,16), 256 thr
// ============================================================
__global__ void k_prep1(const float* __restrict__ Wq, const float* __restrict__ Wk,
                        const float* __restrict__ Wlq, const float* __restrict__ blq) {
    __shared__ float wq_s[64][68];
    __shared__ float wk_s[64][68];
    __shared__ float wl_s[64][4];
    const int h = blockIdx.x, dz = blockIdx.y;
    const int t = threadIdx.x;
    const int rb = h * N_ + dz * 64;

    for (int i = t; i < 64 * 16; i += 256) {
        int r = i >> 4, q = i & 15;
        ((float4*)wq_s[r])[q] = ((const float4*)(Wq + (size_t)(rb + r) * 64))[q];
        ((float4*)wk_s[r])[q] = ((const float4*)(Wk + (size_t)(rb + r) * 64))[q];
    }
    if (t < 64) {
        wl_s[t][0] = Wlq[(size_t)(rb + t) * 3 + 0];
        wl_s[t][1] = Wlq[(size_t)(rb + t) * 3 + 1];
        wl_s[t][2] = Wlq[(size_t)(rb + t) * 3 + 2];
        wl_s[t][3] = blq[rb + t];
    }
    __syncthreads();

    const int rg = t >> 4, cg = t & 15;
    const int c0 = rg * 4, cp0 = cg * 4;
    float acc[4][4] = {};
    #pragma unroll 8
    for (int d = 0; d < 64; d++) {
        float4 qv = *(float4*)&wq_s[d][c0];
        float4 kv = *(float4*)&wk_s[d][cp0];
        acc[0][0]+=qv.x*kv.x; acc[0][1]+=qv.x*kv.y; acc[0][2]+=qv.x*kv.z; acc[0][3]+=qv.x*kv.w;
        acc[1][0]+=qv.y*kv.x; acc[1][1]+=qv.y*kv.y; acc[1][2]+=qv.y*kv.z; acc[1][3]+=qv.y*kv.w;
        acc[2][0]+=qv.z*kv.x; acc[2][1]+=qv.z*kv.y; acc[2][2]+=qv.z*kv.z; acc[2][3]+=qv.z*kv.w;
        acc[3][0]+=qv.w*kv.x; acc[3][1]+=qv.w*kv.y; acc[3][2]+=qv.w*kv.z; acc[3][3]+=qv.w*kv.w;
    }
    #pragma unroll
    for (int i = 0; i < 4; i++)
        *(float4*)&g_Apart[dz][h][c0 + i][cp0] =
            make_float4(acc[i][0], acc[i][1], acc[i][2], acc[i][3]);

    if (t < 64) {
        float s0 = 0.f, s1 = 0.f, s2 = 0.f, s3 = 0.f;
        #pragma unroll 8
        for (int d = 0; d < 64; d++) {
            float wv = wq_s[d][t];
            float4 wl = *(float4*)wl_s[d];
            s0 += wv * wl.x; s1 += wv * wl.y; s2 += wv * wl.z; s3 += wv * wl.w;
        }
        *(float4*)g_bpart[dz][h][t] = make_float4(s0, s1, s2, s3);
    }
}

// ============================================================
// k_prep2: reduce 16 partials. grid (H,16), 256 thr
// ============================================================
__global__ void k_prep2() {
    const int h = blockIdx.x;
    const int e = blockIdx.y * 256 + threadIdx.x;
    const int c = e >> 6, cp = e & 63;
    float s = 0.f;
    #pragma unroll
    for (int dz = 0; dz < 16; dz++) s += g_Apart[dz][h][c][cp];
    g_A[h][c][cp] = s;
    if (blockIdx.y == 0 && threadIdx.x < 64) {
        const int cc = threadIdx.x;
        float4 acc = make_float4(0.f, 0.f, 0.f, 0.f);
        #pragma unroll
        for (int dz = 0; dz < 16; dz++) {
            float4 v = *(float4*)g_bpart[dz][h][cc];
            acc.x += v.x; acc.y += v.y; acc.z += v.z; acc.w += v.w;
        }
        *(float4*)g_Bq4[h][cc] = acc;
    }
}

// ============================================================
// k_wvT: extended transposed V weights. grid 256, 256 thr
// ============================================================
__global__ void k_wvT(const float* __restrict__ Wv, const float* __restrict__ Wlv,
                      const float* __restrict__ blv) {
    __shared__ float tile[32][65];
    const int r0 = blockIdx.x * 32;
    const int t = threadIdx.x;
    for (int i = t; i < 32 * 64; i += 256) {
        int r = i >> 6, c = i & 63;
        tile[r][c] = Wv[(size_t)(r0 + r) * 64 + c];
    }
    __syncthreads();
    for (int i = t; i < 64 * 32; i += 256) {
        int c = i >> 5, r = i & 31;
        g_WvT[c][r0 + r] = tile[r][c];
    }
    if (t < 32) {
        size_t gr = (size_t)(r0 + t);
        g_WvT[64][r0 + t] = Wlv[gr * 3 + 0];
        g_WvT[65][r0 + t] = Wlv[gr * 3 + 1];
        g_WvT[66][r0 + t] = Wlv[gr * 3 + 2];
        g_WvT[67][r0 + t] = blv[gr];
    }
}

// ============================================================
// k_buildG: G = A·ns + Bq·coord + bq. grid (B*H, 16), 256 thr
// ============================================================
__global__ void k_buildG(const float* __restrict__ neighbors,
                         const float* __restrict__ coord) {
    __shared__ float At[64 * 68];
    __shared__ float ns_s[64 * 64];
    __shared__ float cs[3 * 64];
    __shared__ float Bq_s[64 * 4];

    const int b = blockIdx.x >> 3, h = blockIdx.x & 7;
    const int m0 = blockIdx.y * 64;
    const int t = threadIdx.x;

    for (int i = t; i < 64 * 64; i += 256) {
        int c = i >> 6, cp = i & 63;
        At[cp * 68 + c] = g_A[h][c][cp];
    }
    for (int i = t; i < 64 * 16; i += 256) {
        int cp = i >> 4, q = i & 15;
        ((float4*)(ns_s + cp * 64))[q] =
            ((const float4*)(neighbors + ((size_t)b * C_ + cp) * N_ + m0))[q];
    }
    for (int i = t; i < 3 * 16; i += 256) {
        int j = i >> 4, q = i & 15;
        ((float4*)(cs + j * 64))[q] =
            ((const float4*)(coord + ((size_t)b * 3 + j) * N_ + m0))[q];
    }
    for (int i = t; i < 64; i += 256)
        *(float4*)(Bq_s + i * 4) = *(float4*)g_Bq4[h][i];
    __syncthreads();

    const int tc = t >> 5;
    const int tm = t & 31;
    const int c0 = tc * 8;

    float acc[8][2];
    #pragma unroll
    for (int i = 0; i < 8; i++) {
        const int c = c0 + i;
        const float q0 = Bq_s[c * 4], q1 = Bq_s[c * 4 + 1], q2 = Bq_s[c * 4 + 2], bz = Bq_s[c * 4 + 3];
        #pragma unroll
        for (int k = 0; k < 2; k++) {
            const int m = tm * 2 + k;
            acc[i][k] = bz + q0 * cs[m] + q1 * cs[64 + m] + q2 * cs[128 + m];
        }
    }
    #pragma unroll 8
    for (int cp = 0; cp < 64; cp++) {
        float2 nv = ((float2*)(ns_s + cp * 64))[tm];
        float4 a0 = *(float4*)(At + cp * 68 + c0);
        float4 a1 = *(float4*)(At + cp * 68 + c0 + 4);
        acc[0][0]+=a0.x*nv.x; acc[0][1]+=a0.x*nv.y;
        acc[1][0]+=a0.y*nv.x; acc[1][1]+=a0.y*nv.y;
        acc[2][0]+=a0.z*nv.x; acc[2][1]+=a0.z*nv.y;
        acc[3][0]+=a0.w*nv.x; acc[3][1]+=a0.w*nv.y;
        acc[4][0]+=a1.x*nv.x; acc[4][1]+=a1.x*nv.y;
        acc[5][0]+=a1.y*nv.x; acc[5][1]+=a1.y*nv.y;
        acc[6][0]+=a1.z*nv.x; acc[6][1]+=a1.z*nv.y;
        acc[7][0]+=a1.w*nv.x; acc[7][1]+=a1.w*nv.y;
    }
    #pragma unroll
    for (int i = 0; i < 8; i++)
        *((float2*)(&g_G[b][h][c0 + i][m0]) + tm) = make_float2(acc[i][0], acc[i][1]);
}

// ============================================================
// k_main: energy -> softmax -> elementwise V' epilogue
// grid (B*H, N/32), 512 thr; round-4 skeleton + duplicated-x pass1
// ============================================================
struct SM3 {
    float E[32][1028];       // 131584 B
    float xsd[64][64];       //  16384 B  (x duplicated pairs)
    float nse[68][32];       //   8704 B
    float gw[68][256];       //  69632 B   (total 226304 B)
};

__global__ void __launch_bounds__(512, 1) k_main(
    const float* __restrict__ x, const float* __restrict__ neighbors,
    const float* __restrict__ coord, float* __restrict__ out) {
    extern __shared__ char smraw[];
    SM3& s = *reinterpret_cast<SM3*>(smraw);

    const int b = blockIdx.x >> 3, h = blockIdx.x & 7;
    const int n0 = blockIdx.y * 32;
    const int t = threadIdx.x;
    const int w = t >> 5, lane = t & 31;

    for (int i = t; i < 64 * 8; i += 512) {
        int c = i >> 3, q = i & 7;
        float4 v = ((const float4*)(x + ((size_t)b * C_ + c) * N_ + n0))[q];
        *(float4*)&s.xsd[c][q * 8]     = make_float4(v.x, v.x, v.y, v.y);
        *(float4*)&s.xsd[c][q * 8 + 4] = make_float4(v.z, v.z, v.w, v.w);
        ((float4*)s.nse[c])[q] = ((const float4*)(neighbors + ((size_t)b * C_ + c) * N_ + n0))[q];
    }
    if (t < 24) {
        int j = t >> 3, q = t & 7;
        ((float4*)s.nse[64 + j])[q] = ((const float4*)(coord + ((size_t)b * 3 + j) * N_ + n0))[q];
    } else if (t < 32) {
        ((float4*)s.nse[67])[t - 24] = make_float4(1.f, 1.f, 1.f, 1.f);
    }
    // initial G chunk 0 load
    for (int i = t; i < 64 * 64; i += 512) {
        int c = i >> 6, q = i & 63;
        ((float4*)s.gw[c])[q] = ((const float4*)(&g_G[b][h][c][0]))[q];
    }
    __syncthreads();

    // ---- pass 1: E[32][1024], chunks of 256, reg-prefetch, dup-x (no pk2) ----
    {
        const int rg = t >> 6;          // rows rg*4..+3
        const int cg = t & 63;          // cols cg*4..+3
        for (int mc = 0; mc < 4; mc++) {
            float4 pf[8];
            if (mc < 3) {
                #pragma unroll
                for (int q = 0; q < 8; q++) {
                    int idx = q * 512 + t;
                    pf[q] = ((const float4*)(&g_G[b][h][idx >> 6][(mc + 1) * 256]))[idx & 63];
                }
            }
            unsigned long long a01[4] = {}, a23[4] = {};
            #pragma unroll 8
            for (int c = 0; c < 64; c++) {
                float4 xa = *(float4*)&s.xsd[c][rg * 8];
                float4 xb = *(float4*)&s.xsd[c][rg * 8 + 4];
                float4 gv = *(float4*)&s.gw[c][cg * 4];
                unsigned long long g01 = ((unsigned long long*)&gv)[0];
                unsigned long long g23 = ((unsigned long long*)&gv)[1];
                unsigned long long u0 = ((unsigned long long*)&xa)[0];
                unsigned long long u1 = ((unsigned long long*)&xa)[1];
                unsigned long long u2 = ((unsigned long long*)&xb)[0];
                unsigned long long u3 = ((unsigned long long*)&xb)[1];
                fma2(a01[0], u0, g01); fma2(a23[0], u0, g23);
                fma2(a01[1], u1, g01); fma2(a23[1], u1, g23);
                fma2(a01[2], u2, g01); fma2(a23[2], u2, g23);
                fma2(a01[3], u3, g01); fma2(a23[3], u3, g23);
            }
            const int mb = mc * 256 + cg * 4;
            #pragma unroll
            for (int i = 0; i < 4; i++) {
                float4 o;
                ((unsigned long long*)&o)[0] = a01[i];
                ((unsigned long long*)&o)[1] = a23[i];
                *(float4*)&s.E[rg * 4 + i][mb] = o;
            }
            __syncthreads();
            if (mc < 3) {
                #pragma unroll
                for (int q = 0; q < 8; q++) {
                    int idx = q * 512 + t;
                    ((float4*)s.gw[idx >> 6])[idx & 63] = pf[q];
                }
                __syncthreads();
            }
        }
    }

    // ---- softmax: warp w handles rows 2w, 2w+1 ----
    #pragma unroll
    for (int rr = 0; rr < 2; rr++) {
        const int r = w * 2 + rr;
        float pv[32];
        float mx = -1e30f;
        #pragma unroll
        for (int j = 0; j < 32; j++) { pv[j] = s.E[r][lane + 32 * j]; mx = fmaxf(mx, pv[j]); }
        #pragma unroll
        for (int o = 16; o; o >>= 1) mx = fmaxf(mx, __shfl_xor_sync(0xffffffffu, mx, o));
        float ss = 0.f;
        #pragma unroll
        for (int j = 0; j < 32; j++) { pv[j] = __expf((pv[j] - mx) * INV_SCALE); ss += pv[j]; }
        #pragma unroll
        for (int o = 16; o; o >>= 1) ss += __shfl_xor_sync(0xffffffffu, ss, o);
        const float rinv = 1.0f / ss;
        #pragma unroll
        for (int j = 0; j < 32; j++) s.E[r][lane + 32 * j] = pv[j] * rinv;
    }

    // initial WvT chunk 0 load (overlaps other warps' softmax; touches only gw)
    for (int i = t; i < 68 * 64; i += 512) {
        int cc = i >> 6, q = i & 63;
        ((float4*)s.gw[cc])[q] = ((const float4*)(g_WvT[cc] + h * N_))[q];
    }
    __syncthreads();

    // ---- pass 2: V'(K=68) * probs, chunks of 256 d-cols, reg-prefetch ----
    {
        const int dg = w * 4 + (lane >> 3);   // d = dg*4
        const int ng = lane & 7;              // n = ng*4
        const size_t outbase = (size_t)b * 8192 + (size_t)h * N_;
        for (int dc = 0; dc < 4; dc++) {
            float4 pf[9];
            if (dc < 3) {
                #pragma unroll
                for (int q = 0; q < 9; q++) {
                    int idx = q * 512 + t;
                    if (idx < 68 * 64)
                        pf[q] = ((const float4*)(g_WvT[idx >> 6] + h * N_ + (dc + 1) * 256))[idx & 63];
                }
            }
            unsigned long long a01[4] = {}, a23[4] = {};
            #pragma unroll 4
            for (int cc = 0; cc < 68; cc++) {
                float4 xv = *(float4*)&s.nse[cc][ng * 4];
                float4 gv = *(float4*)&s.gw[cc][dg * 4];
                unsigned long long g01 = ((unsigned long long*)&gv)[0];
                unsigned long long g23 = ((unsigned long long*)&gv)[1];
                unsigned long long x0 = pk2(xv.x), x1 = pk2(xv.y), x2 = pk2(xv.z), x3 = pk2(xv.w);
                fma2(a01[0], x0, g01); fma2(a23[0], x0, g23);
                fma2(a01[1], x1, g01); fma2(a23[1], x1, g23);
                fma2(a01[2], x2, g01); fma2(a23[2], x2, g23);
                fma2(a01[3], x3, g01); fma2(a23[3], x3, g23);
            }
            float vc[4][4];
            #pragma unroll
            for (int i = 0; i < 4; i++) {
                float4 Ev = *(float4*)&s.E[ng * 4 + i][dc * 256 + dg * 4];
                unsigned long long e01 = ((unsigned long long*)&Ev)[0];
                unsigned long long e23 = ((unsigned long long*)&Ev)[1];
                mul2(a01[i], a01[i], e01);
                mul2(a23[i], a23[i], e23);
                upk(a01[i], vc[i][0], vc[i][1]);
                upk(a23[i], vc[i][2], vc[i][3]);
            }
            #pragma unroll
            for (int k = 0; k < 4; k++) {
                size_t row = outbase + dc * 256 + dg * 4 + k;
                *(float4*)(out + row * N_ + n0 + ng * 4) =
                    make_float4(vc[0][k], vc[1][k], vc[2][k], vc[3][k]);
            }
            __syncthreads();
            if (dc < 3) {
                #pragma unroll
                for (int q = 0; q < 9; q++) {
                    int idx = q * 512 + t;
                    if (idx < 68 * 64)
                        ((float4*)s.gw[idx >> 6])[idx & 63] = pf[q];
                }
                __syncthreads();
            }
        }
    }
}

// ============================================================
extern "C" void kernel_launch(void* const* d_in, const int* in_sizes, int n_in,
                              void* d_out, int out_size) {
    const float* coordinate = (const float*)d_in[0];
    const float* x          = (const float*)d_in[1];
    const float* neighbors  = (const float*)d_in[2];
    const float* Wq         = (const float*)d_in[3];
    const float* Wk         = (const float*)d_in[4];
    const float* Wv         = (const float*)d_in[5];
    const float* Wlq        = (const float*)d_in[6];
    const float* blq        = (const float*)d_in[7];
    const float* Wlv        = (const float*)d_in[8];
    const float* blv        = (const float*)d_in[9];
    float* out = (float*)d_out;

    static bool attr_set = false;
    if (!attr_set) {
        cudaFuncSetAttribute(k_main, cudaFuncAttributeMaxDynamicSharedMemorySize, 227 * 1024);
        attr_set = true;
    }

    k_prep1<<<dim3(H_, 16), 256>>>(Wq, Wk, Wlq, blq);
    k_prep2<<<dim3(H_, 16), 256>>>();
    k_wvT<<<256, 256>>>(Wv, Wlv, blv);
    k_buildG<<<dim3(B_ * H_, 16), 256>>>(neighbors, coordinate);
    k_main<<<dim3(B_ * H_, 32), 512, sizeof(SM3)>>>(x, neighbors, coordinate, out);
}

// round 10
// speedup vs baseline: 3.3059x; 1.5446x over previous
#include <cuda_runtime.h>
#include <cuda_bf16.h>
#include <math.h>
#include <cstdint>

#define B_ 4
#define H_ 8
#define N_ 1024
#define C_ 64
#define INV_SCALE (1.0f/32.0f)

// ---- device scratch ----
__device__ float g_Apart[16][H_][C_][C_];
__device__ float g_bpart[16][H_][C_][4];
__device__ float g_A[H_][C_][C_];
__device__ float g_Bq4[H_][C_][4];
__device__ float g_WvT4[4][H_ * N_];                    // Wlv cols + blv (fp32)
__device__ __nv_bfloat16 g_Gbf[(size_t)B_*H_*N_*C_];    // [bh][m][c] bf16, 4 MB
__device__ __nv_bfloat16 g_Vh[(size_t)H_*N_*C_];        // Wv hi  [h*N+d][c]
__device__ __nv_bfloat16 g_Vl[(size_t)H_*N_*C_];        // Wv lo

// ---- mma.sync m16n8k16 bf16 (base PTX, works on compute_103) ----
__device__ __forceinline__ void mma_bf16(float* c, const unsigned* a, const unsigned* b) {
    asm volatile(
        "mma.sync.aligned.m16n8k16.row.col.f32.bf16.bf16.f32 "
        "{%0,%1,%2,%3}, {%4,%5,%6,%7}, {%8,%9}, {%0,%1,%2,%3};"
        : "+f"(c[0]), "+f"(c[1]), "+f"(c[2]), "+f"(c[3])
        : "r"(a[0]), "r"(a[1]), "r"(a[2]), "r"(a[3]), "r"(b[0]), "r"(b[1]));
}

// ============================================================
// k_prep1: partial A/Bq/bq per 64-d chunk. grid (H,16), 256 thr
// ============================================================
__global__ void k_prep1(const float* __restrict__ Wq, const float* __restrict__ Wk,
                        const float* __restrict__ Wlq, const float* __restrict__ blq) {
    __shared__ float wq_s[64][68];
    __shared__ float wk_s[64][68];
    __shared__ float wl_s[64][4];
    const int h = blockIdx.x, dz = blockIdx.y;
    const int t = threadIdx.x;
    const int rb = h * N_ + dz * 64;

    for (int i = t; i < 64 * 16; i += 256) {
        int r = i >> 4, q = i & 15;
        ((float4*)wq_s[r])[q] = ((const float4*)(Wq + (size_t)(rb + r) * 64))[q];
        ((float4*)wk_s[r])[q] = ((const float4*)(Wk + (size_t)(rb + r) * 64))[q];
    }
    if (t < 64) {
        wl_s[t][0] = Wlq[(size_t)(rb + t) * 3 + 0];
        wl_s[t][1] = Wlq[(size_t)(rb + t) * 3 + 1];
        wl_s[t][2] = Wlq[(size_t)(rb + t) * 3 + 2];
        wl_s[t][3] = blq[rb + t];
    }
    __syncthreads();

    const int rg = t >> 4, cg = t & 15;
    const int c0 = rg * 4, cp0 = cg * 4;
    float acc[4][4] = {};
    #pragma unroll 8
    for (int d = 0; d < 64; d++) {
        float4 qv = *(float4*)&wq_s[d][c0];
        float4 kv = *(float4*)&wk_s[d][cp0];
        acc[0][0]+=qv.x*kv.x; acc[0][1]+=qv.x*kv.y; acc[0][2]+=qv.x*kv.z; acc[0][3]+=qv.x*kv.w;
        acc[1][0]+=qv.y*kv.x; acc[1][1]+=qv.y*kv.y; acc[1][2]+=qv.y*kv.z; acc[1][3]+=qv.y*kv.w;
        acc[2][0]+=qv.z*kv.x; acc[2][1]+=qv.z*kv.y; acc[2][2]+=qv.z*kv.z; acc[2][3]+=qv.z*kv.w;
        acc[3][0]+=qv.w*kv.x; acc[3][1]+=qv.w*kv.y; acc[3][2]+=qv.w*kv.z; acc[3][3]+=qv.w*kv.w;
    }
    #pragma unroll
    for (int i = 0; i < 4; i++)
        *(float4*)&g_Apart[dz][h][c0 + i][cp0] =
            make_float4(acc[i][0], acc[i][1], acc[i][2], acc[i][3]);

    if (t < 64) {
        float s0 = 0.f, s1 = 0.f, s2 = 0.f, s3 = 0.f;
        #pragma unroll 8
        for (int d = 0; d < 64; d++) {
            float wv = wq_s[d][t];
            float4 wl = *(float4*)wl_s[d];
            s0 += wv * wl.x; s1 += wv * wl.y; s2 += wv * wl.z; s3 += wv * wl.w;
        }
        *(float4*)g_bpart[dz][h][t] = make_float4(s0, s1, s2, s3);
    }
}

// ============================================================
// k_prep2: reduce 16 partials. grid (H,16), 256 thr
// ============================================================
__global__ void k_prep2() {
    const int h = blockIdx.x;
    const int e = blockIdx.y * 256 + threadIdx.x;
    const int c = e >> 6, cp = e & 63;
    float s = 0.f;
    #pragma unroll
    for (int dz = 0; dz < 16; dz++) s += g_Apart[dz][h][c][cp];
    g_A[h][c][cp] = s;
    if (blockIdx.y == 0 && threadIdx.x < 64) {
        const int cc = threadIdx.x;
        float4 acc = make_float4(0.f, 0.f, 0.f, 0.f);
        #pragma unroll
        for (int dz = 0; dz < 16; dz++) {
            float4 v = *(float4*)g_bpart[dz][h][cc];
            acc.x += v.x; acc.y += v.y; acc.z += v.z; acc.w += v.w;
        }
        *(float4*)g_Bq4[h][cc] = acc;
    }
}

// ============================================================
// k_conv: Wv -> split bf16 hi/lo [d][c]; Wlv/blv -> g_WvT4. grid 2048, 256 thr
// ============================================================
__global__ void k_conv(const float* __restrict__ Wv, const float* __restrict__ Wlv,
                       const float* __restrict__ blv) {
    const int i = blockIdx.x * 256 + threadIdx.x;
    float v = Wv[i];
    __nv_bfloat16 hi = __float2bfloat16_rn(v);
    g_Vh[i] = hi;
    g_Vl[i] = __float2bfloat16_rn(v - __bfloat162float(hi));
    if (i < H_ * N_) {
        g_WvT4[0][i] = Wlv[(size_t)i * 3 + 0];
        g_WvT4[1][i] = Wlv[(size_t)i * 3 + 1];
        g_WvT4[2][i] = Wlv[(size_t)i * 3 + 2];
        g_WvT4[3][i] = blv[i];
    }
}

// ============================================================
// k_buildG: G = A·ns + Bq·coord + bq -> bf16 [m][c]. grid (B*H,16), 256 thr
// ============================================================
__global__ void k_buildG(const float* __restrict__ neighbors,
                         const float* __restrict__ coord) {
    __shared__ float At[64 * 68];
    __shared__ float ns_s[64 * 64];
    __shared__ float cs[3 * 64];
    __shared__ float Bq_s[64 * 4];

    const int b = blockIdx.x >> 3, h = blockIdx.x & 7;
    const int m0 = blockIdx.y * 64;
    const int t = threadIdx.x;

    for (int i = t; i < 64 * 64; i += 256) {
        int c = i >> 6, cp = i & 63;
        At[cp * 68 + c] = g_A[h][c][cp];
    }
    for (int i = t; i < 64 * 16; i += 256) {
        int cp = i >> 4, q = i & 15;
        ((float4*)(ns_s + cp * 64))[q] =
            ((const float4*)(neighbors + ((size_t)b * C_ + cp) * N_ + m0))[q];
    }
    for (int i = t; i < 3 * 16; i += 256) {
        int j = i >> 4, q = i & 15;
        ((float4*)(cs + j * 64))[q] =
            ((const float4*)(coord + ((size_t)b * 3 + j) * N_ + m0))[q];
    }
    for (int i = t; i < 64; i += 256)
        *(float4*)(Bq_s + i * 4) = *(float4*)g_Bq4[h][i];
    __syncthreads();

    const int tc = t >> 5;
    const int tm = t & 31;
    const int c0 = tc * 8;

    float acc[8][2];
    #pragma unroll
    for (int i = 0; i < 8; i++) {
        const int c = c0 + i;
        const float q0 = Bq_s[c * 4], q1 = Bq_s[c * 4 + 1], q2 = Bq_s[c * 4 + 2], bz = Bq_s[c * 4 + 3];
        #pragma unroll
        for (int k = 0; k < 2; k++) {
            const int m = tm * 2 + k;
            acc[i][k] = bz + q0 * cs[m] + q1 * cs[64 + m] + q2 * cs[128 + m];
        }
    }
    #pragma unroll 8
    for (int cp = 0; cp < 64; cp++) {
        float2 nv = ((float2*)(ns_s + cp * 64))[tm];
        float4 a0 = *(float4*)(At + cp * 68 + c0);
        float4 a1 = *(float4*)(At + cp * 68 + c0 + 4);
        acc[0][0]+=a0.x*nv.x; acc[0][1]+=a0.x*nv.y;
        acc[1][0]+=a0.y*nv.x; acc[1][1]+=a0.y*nv.y;
        acc[2][0]+=a0.z*nv.x; acc[2][1]+=a0.z*nv.y;
        acc[3][0]+=a0.w*nv.x; acc[3][1]+=a0.w*nv.y;
        acc[4][0]+=a1.x*nv.x; acc[4][1]+=a1.x*nv.y;
        acc[5][0]+=a1.y*nv.x; acc[5][1]+=a1.y*nv.y;
        acc[6][0]+=a1.z*nv.x; acc[6][1]+=a1.z*nv.y;
        acc[7][0]+=a1.w*nv.x; acc[7][1]+=a1.w*nv.y;
    }
    #pragma unroll
    for (int k = 0; k < 2; k++) {
        const int m = m0 + tm * 2 + k;
        __nv_bfloat16 p[8];
        #pragma unroll
        for (int i = 0; i < 8; i++) p[i] = __float2bfloat16_rn(acc[i][k]);
        *(uint4*)(&g_Gbf[(((size_t)b * H_ + h) * N_ + m) * C_ + c0]) = *(uint4*)p;
    }
}

// ============================================================
// k_mmain: mma.sync main kernel. grid (B*H, 32), 512 thr.
// CTA = (b,h, 32 n-rows). E via bf16 MMA, V' via split-bf16 3-MMA.
// ============================================================
#define ESTRIDE 1036
#define SM_E    0
#define SM_X    132608                 // 32*1036*4
#define SM_U    (SM_X + 4608)          // union: G chunk [256][72] / Wvh+Wvl [128][72]x2
#define SM_NH2  (SM_U + 36864)
#define SM_NL2  (SM_NH2 + 4608)
#define SM_WL   (SM_NL2 + 4608)        // wl4 [1024][4] f32
#define SM_C4   (SM_WL + 16384)        // coords4 [32][4] f32
#define SM_TOT  (SM_C4 + 512)          // 200192 B

__global__ void __launch_bounds__(512, 1) k_mmain(
    const float* __restrict__ x, const float* __restrict__ neighbors,
    const float* __restrict__ coordinate, float* __restrict__ out) {
    extern __shared__ char sm[];
    float* Es = (float*)sm;
    __nv_bfloat16* xbf = (__nv_bfloat16*)(sm + SM_X);
    __nv_bfloat16* gsm = (__nv_bfloat16*)(sm + SM_U);      // pass1
    __nv_bfloat16* wvh = (__nv_bfloat16*)(sm + SM_U);      // pass2
    __nv_bfloat16* wvl = (__nv_bfloat16*)(sm + SM_U + 18432);
    __nv_bfloat16* nsh = (__nv_bfloat16*)(sm + SM_NH2);
    __nv_bfloat16* nsl = (__nv_bfloat16*)(sm + SM_NL2);
    float4* wl4 = (float4*)(sm + SM_WL);
    float4* c4  = (float4*)(sm + SM_C4);

    const int b = blockIdx.x >> 3, h = blockIdx.x & 7;
    const int n0 = blockIdx.y * 32;
    const int t = threadIdx.x;
    const int w = t >> 5, l = t & 31;

    // ---- fill xbf [32 n][72 c] and nsT hi/lo [32 n][72 c] ----
    for (int i = t; i < 2048; i += 512) {
        int c = i >> 5, n = i & 31;
        float xv = x[((size_t)b * C_ + c) * N_ + n0 + n];
        float nv = neighbors[((size_t)b * C_ + c) * N_ + n0 + n];
        xbf[n * 72 + c] = __float2bfloat16_rn(xv);
        __nv_bfloat16 hi = __float2bfloat16_rn(nv);
        nsh[n * 72 + c] = hi;
        nsl[n * 72 + c] = __float2bfloat16_rn(nv - __bfloat162float(hi));
    }
    // wl4 and coords
    for (int d = t; d < 1024; d += 512) {
        wl4[d] = make_float4(g_WvT4[0][h * N_ + d], g_WvT4[1][h * N_ + d],
                             g_WvT4[2][h * N_ + d], g_WvT4[3][h * N_ + d]);
    }
    if (t < 32) {
        c4[t] = make_float4(coordinate[((size_t)b * 3 + 0) * N_ + n0 + t],
                            coordinate[((size_t)b * 3 + 1) * N_ + n0 + t],
                            coordinate[((size_t)b * 3 + 2) * N_ + n0 + t], 1.0f);
    }
    __syncthreads();

    // ---- preload X A-fragments: [mt 2][kt 4][4 regs] ----
    unsigned afr[2][4][4];
    #pragma unroll
    for (int mt = 0; mt < 2; mt++)
        #pragma unroll
        for (int kt = 0; kt < 4; kt++) {
            int r0 = mt * 16 + (l >> 2);
            int cc = kt * 16 + ((l & 3) << 1);
            afr[mt][kt][0] = *(unsigned*)(xbf + r0 * 72 + cc);
            afr[mt][kt][1] = *(unsigned*)(xbf + (r0 + 8) * 72 + cc);
            afr[mt][kt][2] = *(unsigned*)(xbf + r0 * 72 + cc + 8);
            afr[mt][kt][3] = *(unsigned*)(xbf + (r0 + 8) * 72 + cc + 8);
        }

    const __nv_bfloat16* gsrc  = g_Gbf + ((size_t)b * H_ + h) * N_ * C_;
    const __nv_bfloat16* vhsrc = g_Vh + (size_t)h * N_ * C_;
    const __nv_bfloat16* vlsrc = g_Vl + (size_t)h * N_ * C_;

    // ---- pass 1: E[32][1024] raw energies, 4 chunks of 256 keys ----
    for (int mc = 0; mc < 4; mc++) {
        for (int i = t; i < 2048; i += 512) {
            int m = i >> 3, q = i & 7;
            *(uint4*)(gsm + m * 72 + q * 8) =
                ((const uint4*)(gsrc + (size_t)(mc * 256 + m) * C_))[q];
        }
        __syncthreads();
        float acc[2][2][4] = {};
        #pragma unroll
        for (int kt = 0; kt < 4; kt++) {
            #pragma unroll
            for (int nt = 0; nt < 2; nt++) {
                int nl = (w << 4) + (nt << 3) + (l >> 2);
                unsigned bb[2];
                bb[0] = *(unsigned*)(gsm + nl * 72 + kt * 16 + ((l & 3) << 1));
                bb[1] = *(unsigned*)(gsm + nl * 72 + kt * 16 + ((l & 3) << 1) + 8);
                mma_bf16(acc[0][nt], afr[0][kt], bb);
                mma_bf16(acc[1][nt], afr[1][kt], bb);
            }
        }
        #pragma unroll
        for (int mt = 0; mt < 2; mt++)
            #pragma unroll
            for (int nt = 0; nt < 2; nt++) {
                int m = mt * 16 + (l >> 2);
                int col = mc * 256 + (w << 4) + (nt << 3) + ((l & 3) << 1);
                *(float2*)(Es + m * ESTRIDE + col) =
                    make_float2(acc[mt][nt][0], acc[mt][nt][1]);
                *(float2*)(Es + (m + 8) * ESTRIDE + col) =
                    make_float2(acc[mt][nt][2], acc[mt][nt][3]);
            }
        __syncthreads();
    }

    // ---- softmax: warp w -> rows 2w, 2w+1 ----
    #pragma unroll
    for (int rr = 0; rr < 2; rr++) {
        const int r = w * 2 + rr;
        float pv[32];
        float mx = -1e30f;
        #pragma unroll
        for (int j = 0; j < 32; j++) { pv[j] = Es[r * ESTRIDE + l + 32 * j]; mx = fmaxf(mx, pv[j]); }
        #pragma unroll
        for (int o = 16; o; o >>= 1) mx = fmaxf(mx, __shfl_xor_sync(0xffffffffu, mx, o));
        float ss = 0.f;
        #pragma unroll
        for (int j = 0; j < 32; j++) { pv[j] = __expf((pv[j] - mx) * INV_SCALE); ss += pv[j]; }
        #pragma unroll
        for (int o = 16; o; o >>= 1) ss += __shfl_xor_sync(0xffffffffu, ss, o);
        const float rinv = 1.0f / ss;
        #pragma unroll
        for (int j = 0; j < 32; j++) Es[r * ESTRIDE + l + 32 * j] = pv[j] * rinv;
    }
    __syncthreads();

    // ---- pass 2: V' (split-bf16 3-MMA) + pos_v + combine + store ----
    const size_t outbase = (size_t)b * 8192 + (size_t)h * N_;
    for (int dc = 0; dc < 8; dc++) {
        for (int i = t; i < 1024; i += 512) {
            int m = i >> 3, q = i & 7;
            *(uint4*)(wvh + m * 72 + q * 8) =
                ((const uint4*)(vhsrc + (size_t)(dc * 128 + m) * C_))[q];
            *(uint4*)(wvl + m * 72 + q * 8) =
                ((const uint4*)(vlsrc + (size_t)(dc * 128 + m) * C_))[q];
        }
        __syncthreads();
        #pragma unroll
        for (int s2 = 0; s2 < 2; s2++) {
            const int task = w * 2 + s2;
            const int mt = task >> 2, nt = task & 3;
            float acc[4] = {};
            #pragma unroll
            for (int kt = 0; kt < 4; kt++) {
                int r0 = mt * 16 + (l >> 2);
                int cc = kt * 16 + ((l & 3) << 1);
                unsigned ah[4], al[4], bh[2], bl[2];
                ah[0] = *(unsigned*)(wvh + r0 * 72 + cc);
                ah[1] = *(unsigned*)(wvh + (r0 + 8) * 72 + cc);
                ah[2] = *(unsigned*)(wvh + r0 * 72 + cc + 8);
                ah[3] = *(unsigned*)(wvh + (r0 + 8) * 72 + cc + 8);
                al[0] = *(unsigned*)(wvl + r0 * 72 + cc);
                al[1] = *(unsigned*)(wvl + (r0 + 8) * 72 + cc);
                al[2] = *(unsigned*)(wvl + r0 * 72 + cc + 8);
                al[3] = *(unsigned*)(wvl + (r0 + 8) * 72 + cc + 8);
                int nl = (nt << 3) + (l >> 2);
                bh[0] = *(unsigned*)(nsh + nl * 72 + cc);
                bh[1] = *(unsigned*)(nsh + nl * 72 + cc + 8);
                bl[0] = *(unsigned*)(nsl + nl * 72 + cc);
                bl[1] = *(unsigned*)(nsl + nl * 72 + cc + 8);
                mma_bf16(acc, ah, bh);
                mma_bf16(acc, ah, bl);
                mma_bf16(acc, al, bh);
            }
            const int d0 = dc * 128 + mt * 16 + (l >> 2);
            const int d1 = d0 + 8;
            const int ncol = (nt << 3) + ((l & 3) << 1);
            float4 wla = wl4[d0], wlb = wl4[d1];
            float4 ca = c4[ncol], cb = c4[ncol + 1];
            float pv00 = wla.x * ca.x + wla.y * ca.y + wla.z * ca.z + wla.w;
            float pv01 = wla.x * cb.x + wla.y * cb.y + wla.z * cb.z + wla.w;
            float pv10 = wlb.x * ca.x + wlb.y * ca.y + wlb.z * ca.z + wlb.w;
            float pv11 = wlb.x * cb.x + wlb.y * cb.y + wlb.z * cb.z + wlb.w;
            float p00 = Es[ncol * ESTRIDE + d0];
            float p01 = Es[(ncol + 1) * ESTRIDE + d0];
            float p10 = Es[ncol * ESTRIDE + d1];
            float p11 = Es[(ncol + 1) * ESTRIDE + d1];
            *(float2*)(out + (outbase + d0) * N_ + n0 + ncol) =
                make_float2(p00 * (acc[0] + pv00), p01 * (acc[1] + pv01));
            *(float2*)(out + (outbase + d1) * N_ + n0 + ncol) =
                make_float2(p10 * (acc[2] + pv10), p11 * (acc[3] + pv11));
        }
        __syncthreads();
    }
}

// ============================================================
extern "C" void kernel_launch(void* const* d_in, const int* in_sizes, int n_in,
                              void* d_out, int out_size) {
    const float* coordinate = (const float*)d_in[0];
    const float* x          = (const float*)d_in[1];
    const float* neighbors  = (const float*)d_in[2];
    const float* Wq         = (const float*)d_in[3];
    const float* Wk         = (const float*)d_in[4];
    const float* Wv         = (const float*)d_in[5];
    const float* Wlq        = (const float*)d_in[6];
    const float* blq        = (const float*)d_in[7];
    const float* Wlv        = (const float*)d_in[8];
    const float* blv        = (const float*)d_in[9];
    float* out = (float*)d_out;

    static bool attr_set = false;
    if (!attr_set) {
        cudaFuncSetAttribute(k_mmain, cudaFuncAttributeMaxDynamicSharedMemorySize, SM_TOT);
        attr_set = true;
    }

    k_prep1<<<dim3(H_, 16), 256>>>(Wq, Wk, Wlq, blq);
    k_prep2<<<dim3(H_, 16), 256>>>();
    k_conv<<<2048, 256>>>(Wv, Wlv, blv);
    k_buildG<<<dim3(B_ * H_, 16), 256>>>(neighbors, coordinate);
    k_mmain<<<dim3(B_ * H_, 32), 512, SM_TOT>>>(x, neighbors, coordinate, out);
}

// round 12
// speedup vs baseline: 3.4398x; 1.0405x over previous
#include <cuda_runtime.h>
#include <cuda_bf16.h>
#include <math.h>
#include <cstdint>

#define B_ 4
#define H_ 8
#define N_ 1024
#define C_ 64
#define INV_SCALE (1.0f/32.0f)

// ---- device scratch ----
__device__ float g_Apart[16][H_][C_][C_];
__device__ float g_bpart[16][H_][C_][4];
__device__ float g_A[H_][C_][C_];
__device__ float g_Bq4[H_][C_][4];
__device__ __nv_bfloat16 g_Gbf[(size_t)B_*H_*N_*C_];    // [bh][m][c] bf16, 4 MB
__device__ __nv_bfloat16 g_Vh[(size_t)H_*N_*80];        // [Wv|Wlv|blv|0] hi, K=80
__device__ __nv_bfloat16 g_Vl[(size_t)H_*N_*80];        // lo

// ---- mma.sync m16n8k16 bf16 (base PTX) ----
__device__ __forceinline__ void mma_bf16(float* c, const unsigned* a, const unsigned* b) {
    asm volatile(
        "mma.sync.aligned.m16n8k16.row.col.f32.bf16.bf16.f32 "
        "{%0,%1,%2,%3}, {%4,%5,%6,%7}, {%8,%9}, {%0,%1,%2,%3};"
        : "+f"(c[0]), "+f"(c[1]), "+f"(c[2]), "+f"(c[3])
        : "r"(a[0]), "r"(a[1]), "r"(a[2]), "r"(a[3]), "r"(b[0]), "r"(b[1]));
}
__device__ __forceinline__ void cp16(unsigned dst, const void* src) {
    asm volatile("cp.async.cg.shared.global [%0], [%1], 16;" :: "r"(dst), "l"(src));
}
__device__ __forceinline__ void cp_commit() {
    asm volatile("cp.async.commit_group;");
}
template<int NN>
__device__ __forceinline__ void cp_wait() {
    asm volatile("cp.async.wait_group %0;" :: "n"(NN) : "memory");
}

// ============================================================
// k_prep1: partial A/Bq/bq per 64-d chunk. grid (H,16), 256 thr
// ============================================================
__global__ void k_prep1(const float* __restrict__ Wq, const float* __restrict__ Wk,
                        const float* __restrict__ Wlq, const float* __restrict__ blq) {
    __shared__ float wq_s[64][68];
    __shared__ float wk_s[64][68];
    __shared__ float wl_s[64][4];
    const int h = blockIdx.x, dz = blockIdx.y;
    const int t = threadIdx.x;
    const int rb = h * N_ + dz * 64;

    for (int i = t; i < 64 * 16; i += 256) {
        int r = i >> 4, q = i & 15;
        ((float4*)wq_s[r])[q] = ((const float4*)(Wq + (size_t)(rb + r) * 64))[q];
        ((float4*)wk_s[r])[q] = ((const float4*)(Wk + (size_t)(rb + r) * 64))[q];
    }
    if (t < 64) {
        wl_s[t][0] = Wlq[(size_t)(rb + t) * 3 + 0];
        wl_s[t][1] = Wlq[(size_t)(rb + t) * 3 + 1];
        wl_s[t][2] = Wlq[(size_t)(rb + t) * 3 + 2];
        wl_s[t][3] = blq[rb + t];
    }
    __syncthreads();

    const int rg = t >> 4, cg = t & 15;
    const int c0 = rg * 4, cp0 = cg * 4;
    float acc[4][4] = {};
    #pragma unroll 8
    for (int d = 0; d < 64; d++) {
        float4 qv = *(float4*)&wq_s[d][c0];
        float4 kv = *(float4*)&wk_s[d][cp0];
        acc[0][0]+=qv.x*kv.x; acc[0][1]+=qv.x*kv.y; acc[0][2]+=qv.x*kv.z; acc[0][3]+=qv.x*kv.w;
        acc[1][0]+=qv.y*kv.x; acc[1][1]+=qv.y*kv.y; acc[1][2]+=qv.y*kv.z; acc[1][3]+=qv.y*kv.w;
        acc[2][0]+=qv.z*kv.x; acc[2][1]+=qv.z*kv.y; acc[2][2]+=qv.z*kv.z; acc[2][3]+=qv.z*kv.w;
        acc[3][0]+=qv.w*kv.x; acc[3][1]+=qv.w*kv.y; acc[3][2]+=qv.w*kv.z; acc[3][3]+=qv.w*kv.w;
    }
    #pragma unroll
    for (int i = 0; i < 4; i++)
        *(float4*)&g_Apart[dz][h][c0 + i][cp0] =
            make_float4(acc[i][0], acc[i][1], acc[i][2], acc[i][3]);

    if (t < 64) {
        float s0 = 0.f, s1 = 0.f, s2 = 0.f, s3 = 0.f;
        #pragma unroll 8
        for (int d = 0; d < 64; d++) {
            float wv = wq_s[d][t];
            float4 wl = *(float4*)wl_s[d];
            s0 += wv * wl.x; s1 += wv * wl.y; s2 += wv * wl.z; s3 += wv * wl.w;
        }
        *(float4*)g_bpart[dz][h][t] = make_float4(s0, s1, s2, s3);
    }
}

// ============================================================
// k_prep2: reduce 16 partials. grid (H,16), 256 thr
// ============================================================
__global__ void k_prep2() {
    const int h = blockIdx.x;
    const int e = blockIdx.y * 256 + threadIdx.x;
    const int c = e >> 6, cp = e & 63;
    float s = 0.f;
    #pragma unroll
    for (int dz = 0; dz < 16; dz++) s += g_Apart[dz][h][c][cp];
    g_A[h][c][cp] = s;
    if (blockIdx.y == 0 && threadIdx.x < 64) {
        const int cc = threadIdx.x;
        float4 acc = make_float4(0.f, 0.f, 0.f, 0.f);
        #pragma unroll
        for (int dz = 0; dz < 16; dz++) {
            float4 v = *(float4*)g_bpart[dz][h][cc];
            acc.x += v.x; acc.y += v.y; acc.z += v.z; acc.w += v.w;
        }
        *(float4*)g_Bq4[h][cc] = acc;
    }
}

// ============================================================
// k_conv2: build extended V weights [d][80] hi/lo. grid 32, 256 thr
// cols 0..63 = Wv, 64..66 = Wlv, 67 = blv, 68..79 = 0
// ============================================================
__global__ void k_conv2(const float* __restrict__ Wv, const float* __restrict__ Wlv,
                        const float* __restrict__ blv) {
    const int d = blockIdx.x * 256 + threadIdx.x;   // 0..8191
    #pragma unroll
    for (int q = 0; q < 10; q++) {
        __nv_bfloat16 hv[8], lv[8];
        #pragma unroll
        for (int k = 0; k < 8; k++) {
            int c = q * 8 + k;
            float v = (c < 64) ? Wv[(size_t)d * 64 + c]
                    : (c < 67) ? Wlv[(size_t)d * 3 + (c - 64)]
                    : (c == 67) ? blv[d] : 0.f;
            __nv_bfloat16 hi = __float2bfloat16_rn(v);
            hv[k] = hi;
            lv[k] = __float2bfloat16_rn(v - __bfloat162float(hi));
        }
        *(uint4*)(&g_Vh[(size_t)d * 80 + q * 8]) = *(uint4*)hv;
        *(uint4*)(&g_Vl[(size_t)d * 80 + q * 8]) = *(uint4*)lv;
    }
}

// ============================================================
// k_buildG: G = A·ns + Bq·coord + bq -> bf16 [m][c]. grid (B*H,16), 256 thr
// ============================================================
__global__ void k_buildG(const float* __restrict__ neighbors,
                         const float* __restrict__ coord) {
    __shared__ float At[64 * 68];
    __shared__ float ns_s[64 * 64];
    __shared__ float cs[3 * 64];
    __shared__ float Bq_s[64 * 4];

    const int b = blockIdx.x >> 3, h = blockIdx.x & 7;
    const int m0 = blockIdx.y * 64;
    const int t = threadIdx.x;

    for (int i = t; i < 64 * 64; i += 256) {
        int c = i >> 6, cp = i & 63;
        At[cp * 68 + c] = g_A[h][c][cp];
    }
    for (int i = t; i < 64 * 16; i += 256) {
        int cp = i >> 4, q = i & 15;
        ((float4*)(ns_s + cp * 64))[q] =
            ((const float4*)(neighbors + ((size_t)b * C_ + cp) * N_ + m0))[q];
    }
    for (int i = t; i < 3 * 16; i += 256) {
        int j = i >> 4, q = i & 15;
        ((float4*)(cs + j * 64))[q] =
            ((const float4*)(coord + ((size_t)b * 3 + j) * N_ + m0))[q];
    }
    for (int i = t; i < 64; i += 256)
        *(float4*)(Bq_s + i * 4) = *(float4*)g_Bq4[h][i];
    __syncthreads();

    const int tc = t >> 5;
    const int tm = t & 31;
    const int c0 = tc * 8;

    float acc[8][2];
    #pragma unroll
    for (int i = 0; i < 8; i++) {
        const int c = c0 + i;
        const float q0 = Bq_s[c * 4], q1 = Bq_s[c * 4 + 1], q2 = Bq_s[c * 4 + 2], bz = Bq_s[c * 4 + 3];
        #pragma unroll
        for (int k = 0; k < 2; k++) {
            const int m = tm * 2 + k;
            acc[i][k] = bz + q0 * cs[m] + q1 * cs[64 + m] + q2 * cs[128 + m];
        }
    }
    #pragma unroll 8
    for (int cp = 0; cp < 64; cp++) {
        float2 nv = ((float2*)(ns_s + cp * 64))[tm];
        float4 a0 = *(float4*)(At + cp * 68 + c0);
        float4 a1 = *(float4*)(At + cp * 68 + c0 + 4);
        acc[0][0]+=a0.x*nv.x; acc[0][1]+=a0.x*nv.y;
        acc[1][0]+=a0.y*nv.x; acc[1][1]+=a0.y*nv.y;
        acc[2][0]+=a0.z*nv.x; acc[2][1]+=a0.z*nv.y;
        acc[3][0]+=a0.w*nv.x; acc[3][1]+=a0.w*nv.y;
        acc[4][0]+=a1.x*nv.x; acc[4][1]+=a1.x*nv.y;
        acc[5][0]+=a1.y*nv.x; acc[5][1]+=a1.y*nv.y;
        acc[6][0]+=a1.z*nv.x; acc[6][1]+=a1.z*nv.y;
        acc[7][0]+=a1.w*nv.x; acc[7][1]+=a1.w*nv.y;
    }
    #pragma unroll
    for (int k = 0; k < 2; k++) {
        const int m = m0 + tm * 2 + k;
        __nv_bfloat16 p[8];
        #pragma unroll
        for (int i = 0; i < 8; i++) p[i] = __float2bfloat16_rn(acc[i][k]);
        *(uint4*)(&g_Gbf[(((size_t)b * H_ + h) * N_ + m) * C_ + c0]) = *(uint4*)p;
    }
}

// ============================================================
// k_mmain: mma.sync main. grid (B*H, 32), 512 thr.
// cp.async double-buffered; pos_v folded into K=80 MMA.
// ============================================================
#define ESTRIDE 1036
#define SM_X    132608                  // Es = [0,132608)
#define SM_NH   (SM_X + 4608)           // ns hi [32][88]
#define SM_NL   (SM_NH + 5632)          // ns lo [32][88]
#define SM_U    (SM_NL + 5632)          // 2 bufs: pass1 gsm 2x36864 / pass2 2x22528
#define SM_TOT  (SM_U + 73728)          // 222208

__global__ void __launch_bounds__(512, 1) k_mmain(
    const float* __restrict__ x, const float* __restrict__ neighbors,
    const float* __restrict__ coordinate, float* __restrict__ out) {
    extern __shared__ char sm[];
    float* Es = (float*)sm;
    __nv_bfloat16* xbf = (__nv_bfloat16*)(sm + SM_X);
    __nv_bfloat16* nsh = (__nv_bfloat16*)(sm + SM_NH);
    __nv_bfloat16* nsl = (__nv_bfloat16*)(sm + SM_NL);
    const unsigned smU = (unsigned)__cvta_generic_to_shared(sm + SM_U);

    const int b = blockIdx.x >> 3, h = blockIdx.x & 7;
    const int n0 = blockIdx.y * 32;
    const int t = threadIdx.x;
    const int w = t >> 5, l = t & 31;

    const __nv_bfloat16* gsrc  = g_Gbf + ((size_t)b * H_ + h) * N_ * C_;
    const __nv_bfloat16* vhsrc = g_Vh + (size_t)h * N_ * 80;
    const __nv_bfloat16* vlsrc = g_Vl + (size_t)h * N_ * 80;

    // prologue: async-copy G chunk 0 -> buf 0
    for (int i = t; i < 2048; i += 512) {
        int r = i >> 3, q = i & 7;
        cp16(smU + (unsigned)(r * 144 + q * 16), gsrc + (size_t)r * C_ + q * 8);
    }
    cp_commit();

    // ---- fill xbf [32][72], ns hi/lo [32][88] (cols 64..67 = coords,1) ----
    for (int i = t; i < 2048; i += 512) {
        int c = i >> 5, n = i & 31;
        float xv = x[((size_t)b * C_ + c) * N_ + n0 + n];
        float nv = neighbors[((size_t)b * C_ + c) * N_ + n0 + n];
        xbf[n * 72 + c] = __float2bfloat16_rn(xv);
        __nv_bfloat16 hi = __float2bfloat16_rn(nv);
        nsh[n * 88 + c] = hi;
        nsl[n * 88 + c] = __float2bfloat16_rn(nv - __bfloat162float(hi));
    }
    for (int i = t; i < 32 * 24; i += 512) {   // cols 64..87
        int n = i / 24, c = 64 + i % 24;
        float v = (c < 67) ? coordinate[((size_t)b * 3 + (c - 64)) * N_ + n0 + n]
                : (c == 67) ? 1.0f : 0.f;
        __nv_bfloat16 hi = __float2bfloat16_rn(v);
        nsh[n * 88 + c] = hi;
        nsl[n * 88 + c] = __float2bfloat16_rn(v - __bfloat162float(hi));
    }
    __syncthreads();

    // ---- preload X A-fragments ----
    unsigned afr[2][4][4];
    #pragma unroll
    for (int mt = 0; mt < 2; mt++)
        #pragma unroll
        for (int kt = 0; kt < 4; kt++) {
            int r0 = mt * 16 + (l >> 2);
            int cc = kt * 16 + ((l & 3) << 1);
            afr[mt][kt][0] = *(unsigned*)(xbf + r0 * 72 + cc);
            afr[mt][kt][1] = *(unsigned*)(xbf + (r0 + 8) * 72 + cc);
            afr[mt][kt][2] = *(unsigned*)(xbf + r0 * 72 + cc + 8);
            afr[mt][kt][3] = *(unsigned*)(xbf + (r0 + 8) * 72 + cc + 8);
        }

    // ---- pass 1: E[32][1024], 4 chunks of 256 keys, double-buffered ----
    for (int mc = 0; mc < 4; mc++) {
        if (mc < 3) {
            const unsigned dstb = smU + (unsigned)(((mc + 1) & 1) * 36864);
            for (int i = t; i < 2048; i += 512) {
                int r = i >> 3, q = i & 7;
                cp16(dstb + (unsigned)(r * 144 + q * 16),
                     gsrc + (size_t)((mc + 1) * 256 + r) * C_ + q * 8);
            }
            cp_commit();
            cp_wait<1>();
        } else {
            cp_wait<0>();
        }
        __syncthreads();
        const __nv_bfloat16* gsm = (const __nv_bfloat16*)(sm + SM_U + (mc & 1) * 36864);
        float acc[2][2][4] = {};
        #pragma unroll
        for (int kt = 0; kt < 4; kt++) {
            #pragma unroll
            for (int nt = 0; nt < 2; nt++) {
                int nl = (w << 4) + (nt << 3) + (l >> 2);
                unsigned bb[2];
                bb[0] = *(unsigned*)(gsm + nl * 72 + kt * 16 + ((l & 3) << 1));
                bb[1] = *(unsigned*)(gsm + nl * 72 + kt * 16 + ((l & 3) << 1) + 8);
                mma_bf16(acc[0][nt], afr[0][kt], bb);
                mma_bf16(acc[1][nt], afr[1][kt], bb);
            }
        }
        #pragma unroll
        for (int mt = 0; mt < 2; mt++)
            #pragma unroll
            for (int nt = 0; nt < 2; nt++) {
                int m = mt * 16 + (l >> 2);
                int col = mc * 256 + (w << 4) + (nt << 3) + ((l & 3) << 1);
                *(float2*)(Es + m * ESTRIDE + col) =
                    make_float2(acc[mt][nt][0], acc[mt][nt][1]);
                *(float2*)(Es + (m + 8) * ESTRIDE + col) =
                    make_float2(acc[mt][nt][2], acc[mt][nt][3]);
            }
        __syncthreads();
    }

    // prologue pass2: chunk 0 -> buf 0  (overlaps softmax)
    for (int i = t; i < 1280; i += 512) {
        int mat = i >= 640, j = mat ? i - 640 : i;
        int r = j / 10, q = j - r * 10;
        const __nv_bfloat16* src = mat ? vlsrc : vhsrc;
        cp16(smU + (unsigned)(mat * 11264 + r * 176 + q * 16),
             src + (size_t)r * 80 + q * 8);
    }
    cp_commit();

    // ---- softmax: warp w -> rows 2w, 2w+1 ----
    #pragma unroll
    for (int rr = 0; rr < 2; rr++) {
        const int r = w * 2 + rr;
        float pv[32];
        float mx = -1e30f;
        #pragma unroll
        for (int j = 0; j < 32; j++) { pv[j] = Es[r * ESTRIDE + l + 32 * j]; mx = fmaxf(mx, pv[j]); }
        #pragma unroll
        for (int o = 16; o; o >>= 1) mx = fmaxf(mx, __shfl_xor_sync(0xffffffffu, mx, o));
        float ss = 0.f;
        #pragma unroll
        for (int j = 0; j < 32; j++) { pv[j] = __expf((pv[j] - mx) * INV_SCALE); ss += pv[j]; }
        #pragma unroll
        for (int o = 16; o; o >>= 1) ss += __shfl_xor_sync(0xffffffffu, ss, o);
        const float rinv = 1.0f / ss;
        #pragma unroll
        for (int j = 0; j < 32; j++) Es[r * ESTRIDE + l + 32 * j] = pv[j] * rinv;
    }

    // ---- pass 2: 16 chunks of 64 d, K=80 3-MMA (pos_v folded), double-buffered ----
    const size_t outbase = (size_t)b * 8192 + (size_t)h * N_;
    const int mt = w >> 2, nt = w & 3;
    for (int dc = 0; dc < 16; dc++) {
        if (dc < 15) {
            const unsigned dstb = smU + (unsigned)(((dc + 1) & 1) * 22528);
            for (int i = t; i < 1280; i += 512) {
                int mat = i >= 640, j = mat ? i - 640 : i;
                int r = j / 10, q = j - r * 10;
                const __nv_bfloat16* src = mat ? vlsrc : vhsrc;
                cp16(dstb + (unsigned)(mat * 11264 + r * 176 + q * 16),
                     src + (size_t)((dc + 1) * 64 + r) * 80 + q * 8);
            }
            cp_commit();
            cp_wait<1>();
        } else {
            cp_wait<0>();
        }
        __syncthreads();
        const __nv_bfloat16* wvh = (const __nv_bfloat16*)(sm + SM_U + (dc & 1) * 22528);
        const __nv_bfloat16* wvl = wvh + 11264 / 2;

        float acc[4] = {};
        #pragma unroll
        for (int kt = 0; kt < 5; kt++) {
            int r0 = mt * 16 + (l >> 2);
            int cc = kt * 16 + ((l & 3) << 1);
            unsigned ah[4], al[4], bh[2], bl[2];
            ah[0] = *(unsigned*)(wvh + r0 * 88 + cc);
            ah[1] = *(unsigned*)(wvh + (r0 + 8) * 88 + cc);
            ah[2] = *(unsigned*)(wvh + r0 * 88 + cc + 8);
            ah[3] = *(unsigned*)(wvh + (r0 + 8) * 88 + cc + 8);
            al[0] = *(unsigned*)(wvl + r0 * 88 + cc);
            al[1] = *(unsigned*)(wvl + (r0 + 8) * 88 + cc);
            al[2] = *(unsigned*)(wvl + r0 * 88 + cc + 8);
            al[3] = *(unsigned*)(wvl + (r0 + 8) * 88 + cc + 8);
            int nl = (nt << 3) + (l >> 2);
            bh[0] = *(unsigned*)(nsh + nl * 88 + cc);
            bh[1] = *(unsigned*)(nsh + nl * 88 + cc + 8);
            bl[0] = *(unsigned*)(nsl + nl * 88 + cc);
            bl[1] = *(unsigned*)(nsl + nl * 88 + cc + 8);
            mma_bf16(acc, ah, bh);
            mma_bf16(acc, ah, bl);
            mma_bf16(acc, al, bh);
        }
        const int d0 = dc * 64 + mt * 16 + (l >> 2);
        const int d1 = d0 + 8;
        const int ncol = (nt << 3) + ((l & 3) << 1);
        float p00 = Es[ncol * ESTRIDE + d0];
        float p01 = Es[(ncol + 1) * ESTRIDE + d0];
        float p10 = Es[ncol * ESTRIDE + d1];
        float p11 = Es[(ncol + 1) * ESTRIDE + d1];
        *(float2*)(out + (outbase + d0) * N_ + n0 + ncol) =
            make_float2(p00 * acc[0], p01 * acc[1]);
        *(float2*)(out + (outbase + d1) * N_ + n0 + ncol) =
            make_float2(p10 * acc[2], p11 * acc[3]);
        __syncthreads();
    }
}

// ============================================================
extern "C" void kernel_launch(void* const* d_in, const int* in_sizes, int n_in,
                              void* d_out, int out_size) {
    const float* coordinate = (const float*)d_in[0];
    const float* x          = (const float*)d_in[1];
    const float* neighbors  = (const float*)d_in[2];
    const float* Wq         = (const float*)d_in[3];
    const float* Wk         = (const float*)d_in[4];
    const float* Wv         = (const float*)d_in[5];
    const float* Wlq        = (const float*)d_in[6];
    const float* blq        = (const float*)d_in[7];
    const float* Wlv        = (const float*)d_in[8];
    const float* blv        = (const float*)d_in[9];
    float* out = (float*)d_out;

    static bool attr_set = false;
    if (!attr_set) {
        cudaFuncSetAttribute(k_mmain, cudaFuncAttributeMaxDynamicSharedMemorySize, SM_TOT);
        attr_set = true;
    }

    k_prep1<<<dim3(H_, 16), 256>>>(Wq, Wk, Wlq, blq);
    k_prep2<<<dim3(H_, 16), 256>>>();
    k_conv2<<<32, 256>>>(Wv, Wlv, blv);
    k_buildG<<<dim3(B_ * H_, 16), 256>>>(neighbors, coordinate);
    k_mmain<<<dim3(B_ * H_, 32), 512, SM_TOT>>>(x, neighbors, coordinate, out);
}

// round 14
// speedup vs baseline: 4.1548x; 1.2079x over previous
#include <cuda_runtime.h>
#include <cuda_bf16.h>
#include <cuda_fp16.h>
#include <math.h>
#include <cstdint>

#define B_ 4
#define H_ 8
#define N_ 1024
#define C_ 64
#define INV_SCALE (1.0f/32.0f)

// ---- device scratch ----
__device__ float g_Apart[16][H_][C_][C_];
__device__ float g_bpart[16][H_][C_][4];
__device__ float g_A[H_][C_][C_];
__device__ float g_Bq4[H_][C_][4];
__device__ __nv_bfloat16 g_Gbf[(size_t)B_*H_*N_*C_];    // [bh][m][c] bf16
__device__ __nv_bfloat16 g_Vh[(size_t)H_*N_*80];        // [Wv|Wlv|blv|0] hi, K=80
__device__ __nv_bfloat16 g_Vl[(size_t)H_*N_*80];        // lo

// ---- mma.sync m16n8k16 bf16 (base PTX) ----
__device__ __forceinline__ void mma_bf16(float* c, const unsigned* a, const unsigned* b) {
    asm volatile(
        "mma.sync.aligned.m16n8k16.row.col.f32.bf16.bf16.f32 "
        "{%0,%1,%2,%3}, {%4,%5,%6,%7}, {%8,%9}, {%0,%1,%2,%3};"
        : "+f"(c[0]), "+f"(c[1]), "+f"(c[2]), "+f"(c[3])
        : "r"(a[0]), "r"(a[1]), "r"(a[2]), "r"(a[3]), "r"(b[0]), "r"(b[1]));
}
__device__ __forceinline__ void cp16(unsigned dst, const void* src) {
    asm volatile("cp.async.cg.shared.global [%0], [%1], 16;" :: "r"(dst), "l"(src));
}
__device__ __forceinline__ void cp_commit() {
    asm volatile("cp.async.commit_group;");
}
template<int NN>
__device__ __forceinline__ void cp_wait() {
    asm volatile("cp.async.wait_group %0;" :: "n"(NN) : "memory");
}

// ============================================================
// k_prep1: partial A/Bq/bq per 64-d chunk. grid (H,16), 256 thr
// ============================================================
__global__ void k_prep1(const float* __restrict__ Wq, const float* __restrict__ Wk,
                        const float* __restrict__ Wlq, const float* __restrict__ blq) {
    __shared__ float wq_s[64][68];
    __shared__ float wk_s[64][68];
    __shared__ float wl_s[64][4];
    const int h = blockIdx.x, dz = blockIdx.y;
    const int t = threadIdx.x;
    const int rb = h * N_ + dz * 64;

    for (int i = t; i < 64 * 16; i += 256) {
        int r = i >> 4, q = i & 15;
        ((float4*)wq_s[r])[q] = ((const float4*)(Wq + (size_t)(rb + r) * 64))[q];
        ((float4*)wk_s[r])[q] = ((const float4*)(Wk + (size_t)(rb + r) * 64))[q];
    }
    if (t < 64) {
        wl_s[t][0] = Wlq[(size_t)(rb + t) * 3 + 0];
        wl_s[t][1] = Wlq[(size_t)(rb + t) * 3 + 1];
        wl_s[t][2] = Wlq[(size_t)(rb + t) * 3 + 2];
        wl_s[t][3] = blq[rb + t];
    }
    __syncthreads();

    const int rg = t >> 4, cg = t & 15;
    const int c0 = rg * 4, cp0 = cg * 4;
    float acc[4][4] = {};
    #pragma unroll 8
    for (int d = 0; d < 64; d++) {
        float4 qv = *(float4*)&wq_s[d][c0];
        float4 kv = *(float4*)&wk_s[d][cp0];
        acc[0][0]+=qv.x*kv.x; acc[0][1]+=qv.x*kv.y; acc[0][2]+=qv.x*kv.z; acc[0][3]+=qv.x*kv.w;
        acc[1][0]+=qv.y*kv.x; acc[1][1]+=qv.y*kv.y; acc[1][2]+=qv.y*kv.z; acc[1][3]+=qv.y*kv.w;
        acc[2][0]+=qv.z*kv.x; acc[2][1]+=qv.z*kv.y; acc[2][2]+=qv.z*kv.z; acc[2][3]+=qv.z*kv.w;
        acc[3][0]+=qv.w*kv.x; acc[3][1]+=qv.w*kv.y; acc[3][2]+=qv.w*kv.z; acc[3][3]+=qv.w*kv.w;
    }
    #pragma unroll
    for (int i = 0; i < 4; i++)
        *(float4*)&g_Apart[dz][h][c0 + i][cp0] =
            make_float4(acc[i][0], acc[i][1], acc[i][2], acc[i][3]);

    if (t < 64) {
        float s0 = 0.f, s1 = 0.f, s2 = 0.f, s3 = 0.f;
        #pragma unroll 8
        for (int d = 0; d < 64; d++) {
            float wv = wq_s[d][t];
            float4 wl = *(float4*)wl_s[d];
            s0 += wv * wl.x; s1 += wv * wl.y; s2 += wv * wl.z; s3 += wv * wl.w;
        }
        *(float4*)g_bpart[dz][h][t] = make_float4(s0, s1, s2, s3);
    }
}

// ============================================================
// k_prep2: reduce 16 partials + build extended V weights (merged conv).
// grid (H,16), 256 thr
// ============================================================
__global__ void k_prep2(const float* __restrict__ Wv, const float* __restrict__ Wlv,
                        const float* __restrict__ blv) {
    const int h = blockIdx.x;
    const int e = blockIdx.y * 256 + threadIdx.x;
    const int c = e >> 6, cp = e & 63;
    float s = 0.f;
    #pragma unroll
    for (int dz = 0; dz < 16; dz++) s += g_Apart[dz][h][c][cp];
    g_A[h][c][cp] = s;
    if (blockIdx.y == 0 && threadIdx.x < 64) {
        const int cc = threadIdx.x;
        float4 acc = make_float4(0.f, 0.f, 0.f, 0.f);
        #pragma unroll
        for (int dz = 0; dz < 16; dz++) {
            float4 v = *(float4*)g_bpart[dz][h][cc];
            acc.x += v.x; acc.y += v.y; acc.z += v.z; acc.w += v.w;
        }
        *(float4*)g_Bq4[h][cc] = acc;
    }
    // merged conv: 128 (y,x) blocks x 64 threads cover all 8192 d rows
    if (threadIdx.x < 64) {
        const int d = (blockIdx.y * 8 + blockIdx.x) * 64 + threadIdx.x;
        #pragma unroll
        for (int q = 0; q < 10; q++) {
            __nv_bfloat16 hv[8], lv[8];
            #pragma unroll
            for (int k = 0; k < 8; k++) {
                int cc2 = q * 8 + k;
                float v = (cc2 < 64) ? Wv[(size_t)d * 64 + cc2]
                        : (cc2 < 67) ? Wlv[(size_t)d * 3 + (cc2 - 64)]
                        : (cc2 == 67) ? blv[d] : 0.f;
                __nv_bfloat16 hi = __float2bfloat16_rn(v);
                hv[k] = hi;
                lv[k] = __float2bfloat16_rn(v - __bfloat162float(hi));
            }
            *(uint4*)(&g_Vh[(size_t)d * 80 + q * 8]) = *(uint4*)hv;
            *(uint4*)(&g_Vl[(size_t)d * 80 + q * 8]) = *(uint4*)lv;
        }
    }
}

// ============================================================
// k_buildG: G = A·ns + Bq·coord + bq -> bf16 [m][c]. grid (B*H,32), 256 thr
// ============================================================
__global__ void k_buildG(const float* __restrict__ neighbors,
                         const float* __restrict__ coord) {
    __shared__ float At[64 * 68];
    __shared__ float ns_s[64 * 32];
    __shared__ float cs[3 * 32];
    __shared__ float Bq_s[64 * 4];

    const int b = blockIdx.x >> 3, h = blockIdx.x & 7;
    const int m0 = blockIdx.y * 32;
    const int t = threadIdx.x;

    for (int i = t; i < 64 * 64; i += 256) {
        int c = i >> 6, cp = i & 63;
        At[cp * 68 + c] = g_A[h][c][cp];
    }
    for (int i = t; i < 64 * 8; i += 256) {
        int cp = i >> 3, q = i & 7;
        ((float4*)(ns_s + cp * 32))[q] =
            ((const float4*)(neighbors + ((size_t)b * C_ + cp) * N_ + m0))[q];
    }
    if (t < 24) {
        int j = t >> 3, q = t & 7;
        ((float4*)(cs + j * 32))[q] =
            ((const float4*)(coord + ((size_t)b * 3 + j) * N_ + m0))[q];
    }
    if (t < 64)
        *(float4*)(Bq_s + t * 4) = *(float4*)g_Bq4[h][t];
    __syncthreads();

    const int tc = t >> 5;
    const int tm = t & 31;
    const int c0 = tc * 8;

    float acc[8];
    #pragma unroll
    for (int i = 0; i < 8; i++) {
        const int c = c0 + i;
        acc[i] = Bq_s[c * 4 + 3] + Bq_s[c * 4] * cs[tm]
               + Bq_s[c * 4 + 1] * cs[32 + tm] + Bq_s[c * 4 + 2] * cs[64 + tm];
    }
    #pragma unroll 8
    for (int cp = 0; cp < 64; cp++) {
        float nv = ns_s[cp * 32 + tm];
        float4 a0 = *(float4*)(At + cp * 68 + c0);
        float4 a1 = *(float4*)(At + cp * 68 + c0 + 4);
        acc[0] += a0.x * nv; acc[1] += a0.y * nv;
        acc[2] += a0.z * nv; acc[3] += a0.w * nv;
        acc[4] += a1.x * nv; acc[5] += a1.y * nv;
        acc[6] += a1.z * nv; acc[7] += a1.w * nv;
    }
    const int m = m0 + tm;
    __nv_bfloat16 p[8];
    #pragma unroll
    for (int i = 0; i < 8; i++) p[i] = __float2bfloat16_rn(acc[i]);
    *(uint4*)(&g_Gbf[(((size_t)b * H_ + h) * N_ + m) * C_ + c0]) = *(uint4*)p;
}

// ============================================================
// k_mmain: mma.sync main. grid (B*H, 16), 512 thr, 64 rows/CTA.
// E stored fp16; softmax = row sums only; p recomputed in pass 2.
// ============================================================
#define ESH 1040
#define SM_ES 0                         // half Es[64][1040] = 133120
#define SM_X  133120                    // bf16 x[64][72]    = 9216
#define SM_NH 142336                    // bf16 ns hi [64][88] = 11264
#define SM_NL 153600                    // bf16 ns lo          = 11264
#define SM_KP 164864                    // float kpart[4][64]  = 1024
#define SM_RI 165888                    // float rsinv[64]     = 256
#define SM_U  166144                    // operand bufs: pass1 2x18432 / pass2 2x22528
#define SM_TOT 211200

__global__ void __launch_bounds__(512, 1) k_mmain(
    const float* __restrict__ x, const float* __restrict__ neighbors,
    const float* __restrict__ coordinate, float* __restrict__ out) {
    extern __shared__ char sm[];
    __half* Es = (__half*)sm;
    __nv_bfloat16* xbf = (__nv_bfloat16*)(sm + SM_X);
    __nv_bfloat16* nsh = (__nv_bfloat16*)(sm + SM_NH);
    __nv_bfloat16* nsl = (__nv_bfloat16*)(sm + SM_NL);
    float* kpart = (float*)(sm + SM_KP);
    float* rsinv = (float*)(sm + SM_RI);
    const unsigned smU = (unsigned)__cvta_generic_to_shared(sm + SM_U);

    const int b = blockIdx.x >> 3, h = blockIdx.x & 7;
    const int n0 = blockIdx.y * 64;
    const int t = threadIdx.x;
    const int w = t >> 5, l = t & 31;

    const __nv_bfloat16* gsrc  = g_Gbf + ((size_t)b * H_ + h) * N_ * C_;
    const __nv_bfloat16* vhsrc = g_Vh + (size_t)h * N_ * 80;
    const __nv_bfloat16* vlsrc = g_Vl + (size_t)h * N_ * 80;

    // prologue: G chunk 0 (128 key rows) -> buf 0
    for (int i = t; i < 1024; i += 512) {
        int r = i >> 3, q = i & 7;
        cp16(smU + (unsigned)(r * 144 + q * 16), gsrc + (size_t)r * C_ + q * 8);
    }
    cp_commit();

    // fill xbf [64][72], ns hi/lo [64][88] (cols 64..67 = coords,1)
    for (int i = t; i < 4096; i += 512) {
        int c = i >> 6, n = i & 63;
        float xv = x[((size_t)b * C_ + c) * N_ + n0 + n];
        float nv = neighbors[((size_t)b * C_ + c) * N_ + n0 + n];
        xbf[n * 72 + c] = __float2bfloat16_rn(xv);
        __nv_bfloat16 hi = __float2bfloat16_rn(nv);
        nsh[n * 88 + c] = hi;
        nsl[n * 88 + c] = __float2bfloat16_rn(nv - __bfloat162float(hi));
    }
    for (int i = t; i < 64 * 24; i += 512) {
        int n = i / 24, c = 64 + i % 24;
        float v = (c < 67) ? coordinate[((size_t)b * 3 + (c - 64)) * N_ + n0 + n]
                : (c == 67) ? 1.0f : 0.f;
        __nv_bfloat16 hi = __float2bfloat16_rn(v);
        nsh[n * 88 + c] = hi;
        nsl[n * 88 + c] = __float2bfloat16_rn(v - __bfloat162float(hi));
    }
    __syncthreads();

    // preload X A-fragments (pass1): warp covers n rows 16*wn..+15
    const int wn = w >> 2, wk = w & 3;
    unsigned afr[4][4];
    #pragma unroll
    for (int kt = 0; kt < 4; kt++) {
        int r0 = wn * 16 + (l >> 2);
        int cc = kt * 16 + ((l & 3) << 1);
        afr[kt][0] = *(unsigned*)(xbf + r0 * 72 + cc);
        afr[kt][1] = *(unsigned*)(xbf + (r0 + 8) * 72 + cc);
        afr[kt][2] = *(unsigned*)(xbf + r0 * 72 + cc + 8);
        afr[kt][3] = *(unsigned*)(xbf + (r0 + 8) * 72 + cc + 8);
    }

    float s0 = 0.f, s1 = 0.f;

    // ---- pass 1: E[64][1024] fp16, 8 chunks of 128 keys, double-buffered ----
    for (int mc = 0; mc < 8; mc++) {
        if (mc < 7) {
            const unsigned dstb = smU + (unsigned)(((mc + 1) & 1) * 18432);
            for (int i = t; i < 1024; i += 512) {
                int r = i >> 3, q = i & 7;
                cp16(dstb + (unsigned)(r * 144 + q * 16),
                     gsrc + (size_t)((mc + 1) * 128 + r) * C_ + q * 8);
            }
            cp_commit();
            cp_wait<1>();
        } else {
            cp_wait<0>();
        }
        __syncthreads();
        const __nv_bfloat16* gsm = (const __nv_bfloat16*)(sm + SM_U + (mc & 1) * 18432);

        float acc[4][4] = {};
        #pragma unroll
        for (int kt = 0; kt < 4; kt++) {
            #pragma unroll
            for (int j = 0; j < 4; j++) {
                int nl = wk * 32 + j * 8 + (l >> 2);
                unsigned bb[2];
                bb[0] = *(unsigned*)(gsm + nl * 72 + kt * 16 + ((l & 3) << 1));
                bb[1] = *(unsigned*)(gsm + nl * 72 + kt * 16 + ((l & 3) << 1) + 8);
                mma_bf16(acc[j], afr[kt], bb);
            }
        }
        const int r0 = wn * 16 + (l >> 2);
        #pragma unroll
        for (int j = 0; j < 4; j++) {
            int key0 = mc * 128 + wk * 32 + j * 8 + ((l & 3) << 1);
            *(__half2*)(Es + r0 * ESH + key0) = __floats2half2_rn(acc[j][0], acc[j][1]);
            *(__half2*)(Es + (r0 + 8) * ESH + key0) = __floats2half2_rn(acc[j][2], acc[j][3]);
            s0 += __expf(acc[j][0] * INV_SCALE) + __expf(acc[j][1] * INV_SCALE);
            s1 += __expf(acc[j][2] * INV_SCALE) + __expf(acc[j][3] * INV_SCALE);
        }
        __syncthreads();
    }

    // pass-2 prologue: W chunk 0 -> buf 0 (overlaps softmax reduce)
    for (int i = t; i < 1280; i += 512) {
        int mat = i >= 640, j = mat ? i - 640 : i;
        int r = j / 10, q = j - r * 10;
        const __nv_bfloat16* src = mat ? vlsrc : vhsrc;
        cp16(smU + (unsigned)(mat * 11264 + r * 176 + q * 16),
             src + (size_t)r * 80 + q * 8);
    }
    cp_commit();

    // softmax reduce: row sums only
    s0 += __shfl_xor_sync(0xffffffffu, s0, 1);
    s0 += __shfl_xor_sync(0xffffffffu, s0, 2);
    s1 += __shfl_xor_sync(0xffffffffu, s1, 1);
    s1 += __shfl_xor_sync(0xffffffffu, s1, 2);
    if ((l & 3) == 0) {
        int r0 = wn * 16 + (l >> 2);
        kpart[wk * 64 + r0] = s0;
        kpart[wk * 64 + r0 + 8] = s1;
    }
    __syncthreads();
    if (t < 64)
        rsinv[t] = 1.0f / (kpart[t] + kpart[64 + t] + kpart[128 + t] + kpart[192 + t]);
    __syncthreads();

    // ---- pass 2: 16 chunks of 64 d, K=80 3-MMA, double-buffered ----
    const int wd = w >> 2, wn2 = w & 3;
    float rsv[2][2];
    #pragma unroll
    for (int nt = 0; nt < 2; nt++) {
        int ncol = wn2 * 16 + nt * 8 + ((l & 3) << 1);
        rsv[nt][0] = rsinv[ncol];
        rsv[nt][1] = rsinv[ncol + 1];
    }
    const size_t outbase = (size_t)b * 8192 + (size_t)h * N_;

    for (int dc = 0; dc < 16; dc++) {
        if (dc < 15) {
            const unsigned dstb = smU + (unsigned)(((dc + 1) & 1) * 22528);
            for (int i = t; i < 1280; i += 512) {
                int mat = i >= 640, j = mat ? i - 640 : i;
                int r = j / 10, q = j - r * 10;
                const __nv_bfloat16* src = mat ? vlsrc : vhsrc;
                cp16(dstb + (unsigned)(mat * 11264 + r * 176 + q * 16),
                     src + (size_t)((dc + 1) * 64 + r) * 80 + q * 8);
            }
            cp_commit();
            cp_wait<1>();
        } else {
            cp_wait<0>();
        }
        __syncthreads();
        const __nv_bfloat16* wvh = (const __nv_bfloat16*)(sm + SM_U + (dc & 1) * 22528);
        const __nv_bfloat16* wvl = wvh + 5632;   // +11264 bytes

        float acc[2][4] = {};
        #pragma unroll
        for (int kt = 0; kt < 5; kt++) {
            int r0 = wd * 16 + (l >> 2);
            int cc = kt * 16 + ((l & 3) << 1);
            unsigned ah[4], al[4];
            ah[0] = *(unsigned*)(wvh + r0 * 88 + cc);
            ah[1] = *(unsigned*)(wvh + (r0 + 8) * 88 + cc);
            ah[2] = *(unsigned*)(wvh + r0 * 88 + cc + 8);
            ah[3] = *(unsigned*)(wvh + (r0 + 8) * 88 + cc + 8);
            al[0] = *(unsigned*)(wvl + r0 * 88 + cc);
            al[1] = *(unsigned*)(wvl + (r0 + 8) * 88 + cc);
            al[2] = *(unsigned*)(wvl + r0 * 88 + cc + 8);
            al[3] = *(unsigned*)(wvl + (r0 + 8) * 88 + cc + 8);
            #pragma unroll
            for (int nt = 0; nt < 2; nt++) {
                int nl = wn2 * 16 + nt * 8 + (l >> 2);
                unsigned bh[2], bl[2];
                bh[0] = *(unsigned*)(nsh + nl * 88 + cc);
                bh[1] = *(unsigned*)(nsh + nl * 88 + cc + 8);
                bl[0] = *(unsigned*)(nsl + nl * 88 + cc);
                bl[1] = *(unsigned*)(nsl + nl * 88 + cc + 8);
                mma_bf16(acc[nt], ah, bh);
                mma_bf16(acc[nt], ah, bl);
                mma_bf16(acc[nt], al, bh);
            }
        }
        #pragma unroll
        for (int nt = 0; nt < 2; nt++) {
            const int d0 = dc * 64 + wd * 16 + (l >> 2);
            const int d1 = d0 + 8;
            const int ncol = wn2 * 16 + nt * 8 + ((l & 3) << 1);
            float e00 = __half2float(Es[ncol * ESH + d0]);
            float e01 = __half2float(Es[(ncol + 1) * ESH + d0]);
            float e10 = __half2float(Es[ncol * ESH + d1]);
            float e11 = __half2float(Es[(ncol + 1) * ESH + d1]);
            float p00 = __expf(e00 * INV_SCALE) * rsv[nt][0];
            float p01 = __expf(e01 * INV_SCALE) * rsv[nt][1];
            float p10 = __expf(e10 * INV_SCALE) * rsv[nt][0];
            float p11 = __expf(e11 * INV_SCALE) * rsv[nt][1];
            *(float2*)(out + (outbase + d0) * N_ + n0 + ncol) =
                make_float2(p00 * acc[nt][0], p01 * acc[nt][1]);
            *(float2*)(out + (outbase + d1) * N_ + n0 + ncol) =
                make_float2(p10 * acc[nt][2], p11 * acc[nt][3]);
        }
        __syncthreads();
    }
}

// ============================================================
extern "C" void kernel_launch(void* const* d_in, const int* in_sizes, int n_in,
                              void* d_out, int out_size) {
    const float* coordinate = (const float*)d_in[0];
    const float* x          = (const float*)d_in[1];
    const float* neighbors  = (const float*)d_in[2];
    const float* Wq         = (const float*)d_in[3];
    const float* Wk         = (const float*)d_in[4];
    const float* Wv         = (const float*)d_in[5];
    const float* Wlq        = (const float*)d_in[6];
    const float* blq        = (const float*)d_in[7];
    const float* Wlv        = (const float*)d_in[8];
    const float* blv        = (const float*)d_in[9];
    float* out = (float*)d_out;

    static bool attr_set = false;
    if (!attr_set) {
        cudaFuncSetAttribute(k_mmain, cudaFuncAttributeMaxDynamicSharedMemorySize, SM_TOT);
        attr_set = true;
    }

    k_prep1<<<dim3(H_, 16), 256>>>(Wq, Wk, Wlq, blq);
    k_prep2<<<dim3(H_, 16), 256>>>(Wv, Wlv, blv);
    k_buildG<<<dim3(B_ * H_, 32), 256>>>(neighbors, coordinate);
    k_mmain<<<dim3(B_ * H_, 16), 512, SM_TOT>>>(x, neighbors, coordinate, out);
}